// round 7
// baseline (speedup 1.0000x reference)
#include <cuda_runtime.h>
#include <cstdint>

#define N_NODES 50000
#define N_EDGES 800000
#define DIM     128
#define LAYERS  5

#define SCAN_CHUNK  256
#define SCAN_BLOCKS ((N_NODES + SCAN_CHUNK - 1) / SCAN_CHUNK)   // 196

// ---------------- scratch (no allocation allowed) ----------------
__device__ float g_h[2][N_NODES * DIM];    // ping-pong hidden buffers
__device__ float g_agg_hi[N_NODES * DIM];  // tf32-hi of aggregation
__device__ float g_agg_lo[N_NODES * DIM];  // tf32-lo residual
__device__ int   g_deg_out[N_NODES];
__device__ int   g_deg_in[N_NODES];
__device__ float g_norm_src[N_NODES];
__device__ int   g_row_ptr[N_NODES + 1];
__device__ int   g_cursor[N_NODES];
__device__ int2  g_csr[N_EDGES];           // .x = src node, .y = weight bits
__device__ int   g_partial[SCAN_BLOCKS];
__device__ float g_Wt[LAYERS * DIM * DIM]; // W rounded to tf32

// ---------------- tf32 helpers ----------------
__device__ __forceinline__ uint32_t to_tf32(float x) {
    uint32_t h;
    asm("cvt.rna.tf32.f32 %0, %1;" : "=r"(h) : "f"(x));
    return h;
}

__device__ __forceinline__ void split_tf32(float x, uint32_t& hi, uint32_t& lo) {
    uint32_t h = to_tf32(x);
    float r = x - __uint_as_float(h);
    hi = h;
    lo = to_tf32(r);
}

__device__ __forceinline__ void mma_tf32(float c[4], const uint32_t a[4],
                                         uint32_t b0, uint32_t b1) {
    asm volatile(
        "mma.sync.aligned.m16n8k8.row.col.f32.tf32.tf32.f32 "
        "{%0,%1,%2,%3}, {%4,%5,%6,%7}, {%8,%9}, {%0,%1,%2,%3};"
        : "+f"(c[0]), "+f"(c[1]), "+f"(c[2]), "+f"(c[3])
        : "r"(a[0]), "r"(a[1]), "r"(a[2]), "r"(a[3]), "r"(b0), "r"(b1));
}

// ---------------- W -> tf32 (once, all layers) ----------------
__global__ void split_w_kernel(const float* __restrict__ W) {
    int i = blockIdx.x * blockDim.x + threadIdx.x;
    if (i < LAYERS * DIM * DIM)
        g_Wt[i] = __uint_as_float(to_tf32(W[i]));
}

// ---------------- degree computation ----------------
__global__ void zero_deg_kernel() {
    int i = blockIdx.x * blockDim.x + threadIdx.x;
    if (i < N_NODES) { g_deg_out[i] = 0; g_deg_in[i] = 0; }
}

__global__ void count_deg_kernel(const int* __restrict__ src,
                                 const int* __restrict__ dst) {
    int e = blockIdx.x * blockDim.x + threadIdx.x;
    if (e < N_EDGES) {
        atomicAdd(&g_deg_out[src[e]], 1);
        atomicAdd(&g_deg_in[dst[e]], 1);
    }
}

// ---------------- decoupled scan: phase A (per-block sums) ----------------
__global__ __launch_bounds__(SCAN_CHUNK)
void scan_partial_kernel() {
    __shared__ int wsum[SCAN_CHUNK / 32];
    int tid  = threadIdx.x;
    int lane = tid & 31;
    int wid  = tid >> 5;
    int i = blockIdx.x * SCAN_CHUNK + tid;
    int v = (i < N_NODES) ? g_deg_in[i] : 0;
    #pragma unroll
    for (int o = 16; o > 0; o >>= 1) v += __shfl_down_sync(0xFFFFFFFFu, v, o);
    if (lane == 0) wsum[wid] = v;
    __syncthreads();
    if (tid == 0) {
        int s = 0;
        #pragma unroll
        for (int w = 0; w < SCAN_CHUNK / 32; w++) s += wsum[w];
        g_partial[blockIdx.x] = s;
    }
}

// ---------------- phase B (1 block: exclusive scan of partials) ----------------
__global__ __launch_bounds__(256)
void scan_offsets_kernel() {
    __shared__ int wsum[8];
    int tid  = threadIdx.x;
    int lane = tid & 31;
    int wid  = tid >> 5;
    int v = (tid < SCAN_BLOCKS) ? g_partial[tid] : 0;
    int orig = v;
    #pragma unroll
    for (int o = 1; o < 32; o <<= 1) {
        int n = __shfl_up_sync(0xFFFFFFFFu, v, o);
        if (lane >= o) v += n;
    }
    if (lane == 31) wsum[wid] = v;
    __syncthreads();
    if (wid == 0 && lane < 8) {
        int s = wsum[lane];
        #pragma unroll
        for (int o = 1; o < 8; o <<= 1) {
            int n = __shfl_up_sync(0xFFu, s, o);
            if (lane >= o) s += n;
        }
        wsum[lane] = s;
    }
    __syncthreads();
    int excl = v - orig + (wid > 0 ? wsum[wid - 1] : 0);
    if (tid < SCAN_BLOCKS) g_partial[tid] = excl;
}

// ---------------- phase C (per-block scan + row_ptr/cursor/norms) --------------
__global__ __launch_bounds__(SCAN_CHUNK)
void scan_write_kernel() {
    __shared__ int wsum[SCAN_CHUNK / 32];
    int tid  = threadIdx.x;
    int lane = tid & 31;
    int wid  = tid >> 5;
    int i = blockIdx.x * SCAN_CHUNK + tid;
    int orig = (i < N_NODES) ? g_deg_in[i] : 0;
    int v = orig;
    #pragma unroll
    for (int o = 1; o < 32; o <<= 1) {
        int n = __shfl_up_sync(0xFFFFFFFFu, v, o);
        if (lane >= o) v += n;
    }
    if (lane == 31) wsum[wid] = v;
    __syncthreads();
    if (wid == 0 && lane < SCAN_CHUNK / 32) {
        int s = wsum[lane];
        #pragma unroll
        for (int o = 1; o < SCAN_CHUNK / 32; o <<= 1) {
            int n = __shfl_up_sync(0xFFu, s, o);
            if (lane >= o) s += n;
        }
        wsum[lane] = s;
    }
    __syncthreads();
    int excl = v - orig + (wid > 0 ? wsum[wid - 1] : 0) + g_partial[blockIdx.x];
    if (i < N_NODES) {
        g_row_ptr[i] = excl;
        g_cursor[i]  = excl;
        if (i == N_NODES - 1) g_row_ptr[N_NODES] = excl + orig;  // == N_EDGES
        g_norm_src[i] = rsqrtf(fmaxf((float)g_deg_out[i], 1.0f));
    }
}

// ---------------- scatter edges into packed CSR with fused edge weight --------
__global__ void scatter_edges_kernel(const int* __restrict__ src,
                                     const int* __restrict__ dst) {
    int e = blockIdx.x * blockDim.x + threadIdx.x;
    if (e < N_EDGES) {
        int s = src[e];
        int d = dst[e];
        int pos = atomicAdd(&g_cursor[d], 1);
        float nd = rsqrtf(fmaxf((float)g_deg_in[d], 1.0f));
        float w  = g_norm_src[s] * nd;
        g_csr[pos] = make_int2(s, __float_as_int(w));
    }
}

// ---------------- SpMM (CSR gather): one warp per dst node ----------------
// Writes agg pre-split into tf32 hi/lo for the tensor-core GEMM.
__global__ __launch_bounds__(256)
void spmm_csr_kernel(const float* __restrict__ feat, int in_sel) {
    int node = blockIdx.x * (blockDim.x >> 5) + (threadIdx.x >> 5);
    if (node >= N_NODES) return;
    int lane = threadIdx.x & 31;

    const float* __restrict__ h = (in_sel < 0) ? feat : g_h[in_sel];
    const int2* __restrict__ csr = g_csr;

    int beg = g_row_ptr[node];
    int end = g_row_ptr[node + 1];

    float4 s0 = make_float4(0.f, 0.f, 0.f, 0.f);
    float4 s1 = make_float4(0.f, 0.f, 0.f, 0.f);
    float4 s2 = make_float4(0.f, 0.f, 0.f, 0.f);
    float4 s3 = make_float4(0.f, 0.f, 0.f, 0.f);

    int i = beg;
    for (; i + 3 < end; i += 4) {
        int2 e0 = csr[i];
        int2 e1 = csr[i + 1];
        int2 e2 = csr[i + 2];
        int2 e3 = csr[i + 3];
        float4 v0 = ((const float4*)(h + (size_t)e0.x * DIM))[lane];
        float4 v1 = ((const float4*)(h + (size_t)e1.x * DIM))[lane];
        float4 v2 = ((const float4*)(h + (size_t)e2.x * DIM))[lane];
        float4 v3 = ((const float4*)(h + (size_t)e3.x * DIM))[lane];
        float w0 = __int_as_float(e0.y);
        float w1 = __int_as_float(e1.y);
        float w2 = __int_as_float(e2.y);
        float w3 = __int_as_float(e3.y);
        s0.x += v0.x * w0; s0.y += v0.y * w0; s0.z += v0.z * w0; s0.w += v0.w * w0;
        s1.x += v1.x * w1; s1.y += v1.y * w1; s1.z += v1.z * w1; s1.w += v1.w * w1;
        s2.x += v2.x * w2; s2.y += v2.y * w2; s2.z += v2.z * w2; s2.w += v2.w * w2;
        s3.x += v3.x * w3; s3.y += v3.y * w3; s3.z += v3.z * w3; s3.w += v3.w * w3;
    }
    for (; i < end; i++) {
        int2 e0 = csr[i];
        float w0 = __int_as_float(e0.y);
        float4 v0 = ((const float4*)(h + (size_t)e0.x * DIM))[lane];
        s0.x += v0.x * w0; s0.y += v0.y * w0; s0.z += v0.z * w0; s0.w += v0.w * w0;
    }

    float4 o;
    o.x = (s0.x + s1.x) + (s2.x + s3.x);
    o.y = (s0.y + s1.y) + (s2.y + s3.y);
    o.z = (s0.z + s1.z) + (s2.z + s3.z);
    o.w = (s0.w + s1.w) + (s2.w + s3.w);

    uint4 hi, lo;
    split_tf32(o.x, hi.x, lo.x);
    split_tf32(o.y, hi.y, lo.y);
    split_tf32(o.z, hi.z, lo.z);
    split_tf32(o.w, hi.w, lo.w);
    ((uint4*)(g_agg_hi + (size_t)node * DIM))[lane] = hi;
    ((uint4*)(g_agg_lo + (size_t)node * DIM))[lane] = lo;
}

// ---------------- tensor-core GEMM: out = relu(agg @ W + b) ----------------
// A compensated (hi+lo from SpMM), B plain tf32. 2 MMAs per tile.
// Tile: BM=64, BN=128. 128 threads = 4 warps (2 M x 2 N), warp tile 32x64.
__global__ __launch_bounds__(128, 5)
void gemm_tf32_kernel(const float* __restrict__ bias_p,
                      float* __restrict__ ext_out,
                      int layer, int out_sel) {
    __shared__ float Ash[64 * 36];    // 64 rows x 32 k (+4 pad), agg hi
    __shared__ float Asl[64 * 36];    // agg lo
    __shared__ float Bs [32 * 136];   // 32 k x 128 n (+8 pad), W tf32

    float* __restrict__ out = (out_sel < 0) ? ext_out : g_h[out_sel];
    const float* __restrict__ Wt = g_Wt + (size_t)layer * DIM * DIM;

    const int tid  = threadIdx.x;
    const int lane = tid & 31;
    const int wrp  = tid >> 5;
    const int wm   = wrp & 1;       // warp's M half (32 rows)
    const int wn   = wrp >> 1;      // warp's N half (64 cols)
    const int gid  = lane >> 2;     // groupID (0..7)
    const int tg   = lane & 3;      // thread-in-group (0..3)
    const int rowBase = blockIdx.x * 64;

    float C[2][8][4];
    #pragma unroll
    for (int mt = 0; mt < 2; mt++)
        #pragma unroll
        for (int nt = 0; nt < 8; nt++)
            #pragma unroll
            for (int q = 0; q < 4; q++) C[mt][nt][q] = 0.0f;

    for (int kc = 0; kc < DIM; kc += 32) {
        if (kc) __syncthreads();   // protect smem reuse

        // stage A hi/lo chunks: 64 rows x 32 k (512 float4 each, 4/thread each)
        #pragma unroll
        for (int it = 0; it < 4; it++) {
            int f  = tid + it * 128;
            int r  = f >> 3;
            int cc = (f & 7) * 4;
            int grow = rowBase + r;
            float4 vh = make_float4(0.f, 0.f, 0.f, 0.f);
            float4 vl = make_float4(0.f, 0.f, 0.f, 0.f);
            if (grow < N_NODES) {
                vh = *(const float4*)&g_agg_hi[(size_t)grow * DIM + kc + cc];
                vl = *(const float4*)&g_agg_lo[(size_t)grow * DIM + kc + cc];
            }
            *(float4*)&Ash[r * 36 + cc] = vh;
            *(float4*)&Asl[r * 36 + cc] = vl;
        }
        // stage W chunk: 32 k x 128 n (1024 float4, 8/thread)
        #pragma unroll
        for (int it = 0; it < 8; it++) {
            int f  = tid + it * 128;
            int kk = f >> 5;
            int nn = (f & 31) * 4;
            *(float4*)&Bs[kk * 136 + nn] =
                *(const float4*)&Wt[(size_t)(kc + kk) * DIM + nn];
        }
        __syncthreads();

        #pragma unroll
        for (int k8 = 0; k8 < 4; k8++) {
            uint32_t ah[2][4], al[2][4];
            #pragma unroll
            for (int mt = 0; mt < 2; mt++) {
                int r0 = wm * 32 + mt * 16 + gid;
                int c0 = k8 * 8 + tg;
                ah[mt][0] = __float_as_uint(Ash[r0 * 36 + c0]);
                ah[mt][1] = __float_as_uint(Ash[(r0 + 8) * 36 + c0]);
                ah[mt][2] = __float_as_uint(Ash[r0 * 36 + c0 + 4]);
                ah[mt][3] = __float_as_uint(Ash[(r0 + 8) * 36 + c0 + 4]);
                al[mt][0] = __float_as_uint(Asl[r0 * 36 + c0]);
                al[mt][1] = __float_as_uint(Asl[(r0 + 8) * 36 + c0]);
                al[mt][2] = __float_as_uint(Asl[r0 * 36 + c0 + 4]);
                al[mt][3] = __float_as_uint(Asl[(r0 + 8) * 36 + c0 + 4]);
            }
            #pragma unroll
            for (int nt = 0; nt < 8; nt++) {
                int n = wn * 64 + nt * 8 + gid;
                int k = k8 * 8 + tg;
                uint32_t b0 = __float_as_uint(Bs[k * 136 + n]);
                uint32_t b1 = __float_as_uint(Bs[(k + 4) * 136 + n]);
                #pragma unroll
                for (int mt = 0; mt < 2; mt++) {
                    mma_tf32(C[mt][nt], al[mt], b0, b1);   // lo * B
                    mma_tf32(C[mt][nt], ah[mt], b0, b1);   // hi * B
                }
            }
        }
    }

    // epilogue: bias + relu, float2 stores
    #pragma unroll
    for (int nt = 0; nt < 8; nt++) {
        int col = wn * 64 + nt * 8 + 2 * tg;
        float b0 = bias_p[col];
        float b1 = bias_p[col + 1];
        #pragma unroll
        for (int mt = 0; mt < 2; mt++) {
            int row = rowBase + wm * 32 + mt * 16 + gid;
            if (row < N_NODES) {
                float2 o;
                o.x = fmaxf(C[mt][nt][0] + b0, 0.f);
                o.y = fmaxf(C[mt][nt][1] + b1, 0.f);
                *(float2*)&out[(size_t)row * DIM + col] = o;
            }
            if (row + 8 < N_NODES) {
                float2 o;
                o.x = fmaxf(C[mt][nt][2] + b0, 0.f);
                o.y = fmaxf(C[mt][nt][3] + b1, 0.f);
                *(float2*)&out[(size_t)(row + 8) * DIM + col] = o;
            }
        }
    }
}

// ---------------- launch ----------------
extern "C" void kernel_launch(void* const* d_in, const int* in_sizes, int n_in,
                              void* d_out, int out_size) {
    const float* feat = (const float*)d_in[0];   // [N, D]
    const int*   src  = (const int*)d_in[1];     // [E]
    const int*   dst  = (const int*)d_in[2];     // [E]
    const float* W    = (const float*)d_in[3];   // [L, D, D]
    const float* b    = (const float*)d_in[4];   // [L, D]
    float* out = (float*)d_out;                  // [N, D]

    (void)in_sizes; (void)n_in; (void)out_size;

    // ---- one-time CSR build + W convert (per launch, graph-capturable) ----
    zero_deg_kernel<<<(N_NODES + 255) / 256, 256>>>();
    count_deg_kernel<<<(N_EDGES + 255) / 256, 256>>>(src, dst);
    scan_partial_kernel<<<SCAN_BLOCKS, SCAN_CHUNK>>>();
    scan_offsets_kernel<<<1, 256>>>();
    scan_write_kernel<<<SCAN_BLOCKS, SCAN_CHUNK>>>();
    scatter_edges_kernel<<<(N_EDGES + 255) / 256, 256>>>(src, dst);
    split_w_kernel<<<(LAYERS * DIM * DIM + 255) / 256, 256>>>(W);

    const int warps_per_block = 256 / 32;
    const int spmm_blocks = (N_NODES + warps_per_block - 1) / warps_per_block;
    const int gemm_blocks = (N_NODES + 63) / 64;   // 782

    for (int l = 0; l < LAYERS; l++) {
        int in_sel  = (l == 0) ? -1 : ((l - 1) & 1);
        int out_sel = (l == LAYERS - 1) ? -1 : (l & 1);

        spmm_csr_kernel<<<spmm_blocks, 256>>>(feat, in_sel);
        gemm_tf32_kernel<<<gemm_blocks, 128>>>(
            b + (size_t)l * DIM, out, l, out_sel);
    }
}

// round 9
// speedup vs baseline: 1.2009x; 1.2009x over previous
#include <cuda_runtime.h>
#include <cuda_bf16.h>
#include <cstdint>

#define N_NODES 50000
#define N_EDGES 800000
#define DIM     128
#define LAYERS  5

#define SCAN_CHUNK  256
#define SCAN_BLOCKS ((N_NODES + SCAN_CHUNK - 1) / SCAN_CHUNK)   // 196

// ---------------- scratch (no allocation allowed) ----------------
__device__ float    g_h[2][N_NODES * DIM];      // ping-pong hidden (fp32)
__device__ unsigned g_agg_pk[N_NODES * DIM];    // agg packed (lo<<16)|hi bf16
__device__ unsigned g_W_pk[LAYERS * DIM * DIM]; // W packed [l][k][n]
__device__ int      g_deg_out[N_NODES];
__device__ int      g_deg_in[N_NODES];
__device__ float    g_norm_src[N_NODES];
__device__ int      g_row_ptr[N_NODES + 1];
__device__ int      g_cursor[N_NODES];
__device__ int2     g_csr[N_EDGES];
__device__ int      g_partial[SCAN_BLOCKS];

// ---------------- bf16 hi/lo packing ----------------
__device__ __forceinline__ unsigned pack_bf16x2(float x) {
    __nv_bfloat16 h = __float2bfloat16(x);
    float r = x - __bfloat162float(h);
    __nv_bfloat16 l = __float2bfloat16(r);
    return ((unsigned)__bfloat16_as_ushort(l) << 16) |
            (unsigned)__bfloat16_as_ushort(h);
}

// bf16 mma: D(16x8,f32) += A(16x16,bf16) * B(16x8,bf16)
__device__ __forceinline__ void mma_bf16(float c[4], const uint32_t a[4],
                                         uint32_t b0, uint32_t b1) {
    asm volatile(
        "mma.sync.aligned.m16n8k16.row.col.f32.bf16.bf16.f32 "
        "{%0,%1,%2,%3}, {%4,%5,%6,%7}, {%8,%9}, {%0,%1,%2,%3};"
        : "+f"(c[0]), "+f"(c[1]), "+f"(c[2]), "+f"(c[3])
        : "r"(a[0]), "r"(a[1]), "r"(a[2]), "r"(a[3]), "r"(b0), "r"(b1));
}

// ---------------- W -> packed bf16 hi/lo (layout unchanged [l][k][n]) --------
__global__ void split_w_kernel(const float* __restrict__ W) {
    int i = blockIdx.x * blockDim.x + threadIdx.x;
    if (i < LAYERS * DIM * DIM)
        g_W_pk[i] = pack_bf16x2(W[i]);
}

// ---------------- degree computation ----------------
__global__ void zero_deg_kernel() {
    int i = blockIdx.x * blockDim.x + threadIdx.x;
    if (i < N_NODES) { g_deg_out[i] = 0; g_deg_in[i] = 0; }
}

__global__ void count_deg_kernel(const int* __restrict__ src,
                                 const int* __restrict__ dst) {
    int e = blockIdx.x * blockDim.x + threadIdx.x;
    if (e < N_EDGES) {
        atomicAdd(&g_deg_out[src[e]], 1);
        atomicAdd(&g_deg_in[dst[e]], 1);
    }
}

// ---------------- decoupled scan ----------------
__global__ __launch_bounds__(SCAN_CHUNK)
void scan_partial_kernel() {
    __shared__ int wsum[SCAN_CHUNK / 32];
    int tid = threadIdx.x, lane = tid & 31, wid = tid >> 5;
    int i = blockIdx.x * SCAN_CHUNK + tid;
    int v = (i < N_NODES) ? g_deg_in[i] : 0;
    #pragma unroll
    for (int o = 16; o > 0; o >>= 1) v += __shfl_down_sync(0xFFFFFFFFu, v, o);
    if (lane == 0) wsum[wid] = v;
    __syncthreads();
    if (tid == 0) {
        int s = 0;
        #pragma unroll
        for (int w = 0; w < SCAN_CHUNK / 32; w++) s += wsum[w];
        g_partial[blockIdx.x] = s;
    }
}

__global__ __launch_bounds__(256)
void scan_offsets_kernel() {
    __shared__ int wsum[8];
    int tid = threadIdx.x, lane = tid & 31, wid = tid >> 5;
    int v = (tid < SCAN_BLOCKS) ? g_partial[tid] : 0;
    int orig = v;
    #pragma unroll
    for (int o = 1; o < 32; o <<= 1) {
        int n = __shfl_up_sync(0xFFFFFFFFu, v, o);
        if (lane >= o) v += n;
    }
    if (lane == 31) wsum[wid] = v;
    __syncthreads();
    if (wid == 0 && lane < 8) {
        int s = wsum[lane];
        #pragma unroll
        for (int o = 1; o < 8; o <<= 1) {
            int n = __shfl_up_sync(0xFFu, s, o);
            if (lane >= o) s += n;
        }
        wsum[lane] = s;
    }
    __syncthreads();
    int excl = v - orig + (wid > 0 ? wsum[wid - 1] : 0);
    if (tid < SCAN_BLOCKS) g_partial[tid] = excl;
}

__global__ __launch_bounds__(SCAN_CHUNK)
void scan_write_kernel() {
    __shared__ int wsum[SCAN_CHUNK / 32];
    int tid = threadIdx.x, lane = tid & 31, wid = tid >> 5;
    int i = blockIdx.x * SCAN_CHUNK + tid;
    int orig = (i < N_NODES) ? g_deg_in[i] : 0;
    int v = orig;
    #pragma unroll
    for (int o = 1; o < 32; o <<= 1) {
        int n = __shfl_up_sync(0xFFFFFFFFu, v, o);
        if (lane >= o) v += n;
    }
    if (lane == 31) wsum[wid] = v;
    __syncthreads();
    if (wid == 0 && lane < SCAN_CHUNK / 32) {
        int s = wsum[lane];
        #pragma unroll
        for (int o = 1; o < SCAN_CHUNK / 32; o <<= 1) {
            int n = __shfl_up_sync(0xFFu, s, o);
            if (lane >= o) s += n;
        }
        wsum[lane] = s;
    }
    __syncthreads();
    int excl = v - orig + (wid > 0 ? wsum[wid - 1] : 0) + g_partial[blockIdx.x];
    if (i < N_NODES) {
        g_row_ptr[i] = excl;
        g_cursor[i]  = excl;
        if (i == N_NODES - 1) g_row_ptr[N_NODES] = excl + orig;
        g_norm_src[i] = rsqrtf(fmaxf((float)g_deg_out[i], 1.0f));
    }
}

__global__ void scatter_edges_kernel(const int* __restrict__ src,
                                     const int* __restrict__ dst) {
    int e = blockIdx.x * blockDim.x + threadIdx.x;
    if (e < N_EDGES) {
        int s = src[e];
        int d = dst[e];
        int pos = atomicAdd(&g_cursor[d], 1);
        float nd = rsqrtf(fmaxf((float)g_deg_in[d], 1.0f));
        g_csr[pos] = make_int2(s, __float_as_int(g_norm_src[s] * nd));
    }
}

// ---------------- SpMM (CSR gather): one warp per dst node ----------------
// fp32 accumulate; store packed bf16 hi/lo for the bf16 tensor GEMM.
__global__ __launch_bounds__(256)
void spmm_csr_kernel(const float* __restrict__ feat, int in_sel) {
    int node = blockIdx.x * (blockDim.x >> 5) + (threadIdx.x >> 5);
    if (node >= N_NODES) return;
    int lane = threadIdx.x & 31;

    const float* __restrict__ h = (in_sel < 0) ? feat : g_h[in_sel];
    const int2* __restrict__ csr = g_csr;

    int beg = g_row_ptr[node];
    int end = g_row_ptr[node + 1];

    float4 s0 = make_float4(0.f, 0.f, 0.f, 0.f);
    float4 s1 = make_float4(0.f, 0.f, 0.f, 0.f);
    float4 s2 = make_float4(0.f, 0.f, 0.f, 0.f);
    float4 s3 = make_float4(0.f, 0.f, 0.f, 0.f);

    int i = beg;
    for (; i + 3 < end; i += 4) {
        int2 e0 = csr[i];
        int2 e1 = csr[i + 1];
        int2 e2 = csr[i + 2];
        int2 e3 = csr[i + 3];
        float4 v0 = ((const float4*)(h + (size_t)e0.x * DIM))[lane];
        float4 v1 = ((const float4*)(h + (size_t)e1.x * DIM))[lane];
        float4 v2 = ((const float4*)(h + (size_t)e2.x * DIM))[lane];
        float4 v3 = ((const float4*)(h + (size_t)e3.x * DIM))[lane];
        float w0 = __int_as_float(e0.y);
        float w1 = __int_as_float(e1.y);
        float w2 = __int_as_float(e2.y);
        float w3 = __int_as_float(e3.y);
        s0.x += v0.x * w0; s0.y += v0.y * w0; s0.z += v0.z * w0; s0.w += v0.w * w0;
        s1.x += v1.x * w1; s1.y += v1.y * w1; s1.z += v1.z * w1; s1.w += v1.w * w1;
        s2.x += v2.x * w2; s2.y += v2.y * w2; s2.z += v2.z * w2; s2.w += v2.w * w2;
        s3.x += v3.x * w3; s3.y += v3.y * w3; s3.z += v3.z * w3; s3.w += v3.w * w3;
    }
    for (; i < end; i++) {
        int2 e0 = csr[i];
        float w0 = __int_as_float(e0.y);
        float4 v0 = ((const float4*)(h + (size_t)e0.x * DIM))[lane];
        s0.x += v0.x * w0; s0.y += v0.y * w0; s0.z += v0.z * w0; s0.w += v0.w * w0;
    }

    float4 o;
    o.x = (s0.x + s1.x) + (s2.x + s3.x);
    o.y = (s0.y + s1.y) + (s2.y + s3.y);
    o.z = (s0.z + s1.z) + (s2.z + s3.z);
    o.w = (s0.w + s1.w) + (s2.w + s3.w);

    uint4 pk;
    pk.x = pack_bf16x2(o.x);
    pk.y = pack_bf16x2(o.y);
    pk.z = pack_bf16x2(o.z);
    pk.w = pack_bf16x2(o.w);
    ((uint4*)(g_agg_pk + (size_t)node * DIM))[lane] = pk;
}

// ---------------- bf16 tensor GEMM: out = relu(agg @ W + b) ----------------
// 3-pass error-compensated bf16: Ahi*Bhi + Ahi*Blo + Alo*Bhi, fp32 accum.
// Tile: BM=64, BN=128. 128 threads = 4 warps (2M x 2N), warp tile 32x64.
__global__ __launch_bounds__(128, 4)
void gemm_bf16_kernel(const float* __restrict__ bias_p,
                      float* __restrict__ ext_out,
                      int layer, int out_sel) {
    __shared__ uint32_t Apk[64 * 36];   // 64 rows x 32 k packed (+4 pad)
    __shared__ uint32_t Wpk[32 * 132];  // 32 k x 128 n packed (+4 pad)

    float* __restrict__ out = (out_sel < 0) ? ext_out : g_h[out_sel];
    const unsigned* __restrict__ Wp = g_W_pk + (size_t)layer * DIM * DIM;

    const int tid  = threadIdx.x;
    const int lane = tid & 31;
    const int wrp  = tid >> 5;
    const int wm   = wrp & 1;       // warp's M half (32 rows)
    const int wn   = wrp >> 1;      // warp's N half (64 cols)
    const int gid  = lane >> 2;     // groupID (0..7)
    const int tg   = lane & 3;      // thread-in-group (0..3)
    const int rowBase = blockIdx.x * 64;

    float C[2][8][4];
    #pragma unroll
    for (int mt = 0; mt < 2; mt++)
        #pragma unroll
        for (int nt = 0; nt < 8; nt++)
            #pragma unroll
            for (int q = 0; q < 4; q++) C[mt][nt][q] = 0.0f;

    for (int kc = 0; kc < DIM; kc += 32) {
        if (kc) __syncthreads();   // protect smem reuse

        // stage A chunk: 64 rows x 32 k packed (512 uint4, 4/thread)
        #pragma unroll
        for (int it = 0; it < 4; it++) {
            int f  = tid + it * 128;
            int r  = f >> 3;
            int cc = (f & 7) * 4;
            int grow = rowBase + r;
            uint4 v = make_uint4(0u, 0u, 0u, 0u);
            if (grow < N_NODES)
                v = *(const uint4*)&g_agg_pk[(size_t)grow * DIM + kc + cc];
            *(uint4*)&Apk[r * 36 + cc] = v;
        }
        // stage W chunk: 32 k x 128 n packed (1024 uint4, 8/thread)
        #pragma unroll
        for (int it = 0; it < 8; it++) {
            int f  = tid + it * 128;
            int kk = f >> 5;
            int nn = (f & 31) * 4;
            *(uint4*)&Wpk[kk * 132 + nn] =
                *(const uint4*)&Wp[(size_t)(kc + kk) * DIM + nn];
        }
        __syncthreads();

        #pragma unroll
        for (int k16 = 0; k16 < 32; k16 += 16) {
            // A fragments (hi/lo) for this warp's 2 m16 tiles
            uint32_t ah[2][4], al[2][4];
            #pragma unroll
            for (int mt = 0; mt < 2; mt++) {
                int r0 = wm * 32 + mt * 16 + gid;
                int c0 = k16 + tg * 2;
                uint32_t p00 = Apk[r0 * 36 + c0];
                uint32_t p01 = Apk[r0 * 36 + c0 + 1];
                uint32_t p10 = Apk[(r0 + 8) * 36 + c0];
                uint32_t p11 = Apk[(r0 + 8) * 36 + c0 + 1];
                uint32_t p20 = Apk[r0 * 36 + c0 + 8];
                uint32_t p21 = Apk[r0 * 36 + c0 + 9];
                uint32_t p30 = Apk[(r0 + 8) * 36 + c0 + 8];
                uint32_t p31 = Apk[(r0 + 8) * 36 + c0 + 9];
                ah[mt][0] = __byte_perm(p00, p01, 0x5410);
                al[mt][0] = __byte_perm(p00, p01, 0x7632);
                ah[mt][1] = __byte_perm(p10, p11, 0x5410);
                al[mt][1] = __byte_perm(p10, p11, 0x7632);
                ah[mt][2] = __byte_perm(p20, p21, 0x5410);
                al[mt][2] = __byte_perm(p20, p21, 0x7632);
                ah[mt][3] = __byte_perm(p30, p31, 0x5410);
                al[mt][3] = __byte_perm(p30, p31, 0x7632);
            }
            #pragma unroll
            for (int nt = 0; nt < 8; nt++) {
                int n = wn * 64 + nt * 8 + gid;
                int k = k16 + tg * 2;
                uint32_t q00 = Wpk[k * 132 + n];
                uint32_t q01 = Wpk[(k + 1) * 132 + n];
                uint32_t q10 = Wpk[(k + 8) * 132 + n];
                uint32_t q11 = Wpk[(k + 9) * 132 + n];
                uint32_t bh0 = __byte_perm(q00, q01, 0x5410);
                uint32_t bl0 = __byte_perm(q00, q01, 0x7632);
                uint32_t bh1 = __byte_perm(q10, q11, 0x5410);
                uint32_t bl1 = __byte_perm(q10, q11, 0x7632);
                #pragma unroll
                for (int mt = 0; mt < 2; mt++) {
                    mma_bf16(C[mt][nt], ah[mt], bh0, bh1);   // hi*hi
                    mma_bf16(C[mt][nt], ah[mt], bl0, bl1);   // hi*lo
                    mma_bf16(C[mt][nt], al[mt], bh0, bh1);   // lo*hi
                }
            }
        }
    }

    // epilogue: bias + relu, float2 stores
    #pragma unroll
    for (int nt = 0; nt < 8; nt++) {
        int col = wn * 64 + nt * 8 + 2 * tg;
        float b0 = bias_p[col];
        float b1 = bias_p[col + 1];
        #pragma unroll
        for (int mt = 0; mt < 2; mt++) {
            int row = rowBase + wm * 32 + mt * 16 + gid;
            if (row < N_NODES) {
                float2 o;
                o.x = fmaxf(C[mt][nt][0] + b0, 0.f);
                o.y = fmaxf(C[mt][nt][1] + b1, 0.f);
                *(float2*)&out[(size_t)row * DIM + col] = o;
            }
            if (row + 8 < N_NODES) {
                float2 o;
                o.x = fmaxf(C[mt][nt][2] + b0, 0.f);
                o.y = fmaxf(C[mt][nt][3] + b1, 0.f);
                *(float2*)&out[(size_t)(row + 8) * DIM + col] = o;
            }
        }
    }
}

// ---------------- launch ----------------
extern "C" void kernel_launch(void* const* d_in, const int* in_sizes, int n_in,
                              void* d_out, int out_size) {
    const float* feat = (const float*)d_in[0];   // [N, D]
    const int*   src  = (const int*)d_in[1];     // [E]
    const int*   dst  = (const int*)d_in[2];     // [E]
    const float* W    = (const float*)d_in[3];   // [L, D, D]
    const float* b    = (const float*)d_in[4];   // [L, D]
    float* out = (float*)d_out;                  // [N, D]

    (void)in_sizes; (void)n_in; (void)out_size;

    // ---- one-time CSR build + W pack (per launch, graph-capturable) ----
    zero_deg_kernel<<<(N_NODES + 255) / 256, 256>>>();
    count_deg_kernel<<<(N_EDGES + 255) / 256, 256>>>(src, dst);
    scan_partial_kernel<<<SCAN_BLOCKS, SCAN_CHUNK>>>();
    scan_offsets_kernel<<<1, 256>>>();
    scan_write_kernel<<<SCAN_BLOCKS, SCAN_CHUNK>>>();
    scatter_edges_kernel<<<(N_EDGES + 255) / 256, 256>>>(src, dst);
    split_w_kernel<<<(LAYERS * DIM * DIM + 255) / 256, 256>>>(W);

    const int warps_per_block = 256 / 32;
    const int spmm_blocks = (N_NODES + warps_per_block - 1) / warps_per_block;
    const int gemm_blocks = (N_NODES + 63) / 64;   // 782

    for (int l = 0; l < LAYERS; l++) {
        int in_sel  = (l == 0) ? -1 : ((l - 1) & 1);
        int out_sel = (l == LAYERS - 1) ? -1 : (l & 1);

        spmm_csr_kernel<<<spmm_blocks, 256>>>(feat, in_sel);
        gemm_bf16_kernel<<<gemm_blocks, 128>>>(
            b + (size_t)l * DIM, out, l, out_sel);
    }
}

// round 10
// speedup vs baseline: 1.2831x; 1.0685x over previous
#include <cuda_runtime.h>
#include <cuda_bf16.h>
#include <cuda_fp16.h>
#include <cstdint>

#define N_NODES 50000
#define N_EDGES 800000
#define DIM     128
#define DIM2    64                    // DIM/2 (half2 / packed units per row)
#define LAYERS  5

#define SCAN_CHUNK  256
#define SCAN_BLOCKS ((N_NODES + SCAN_CHUNK - 1) / SCAN_CHUNK)   // 196

// ---------------- scratch (no allocation allowed) ----------------
__device__ unsigned g_feat16[N_NODES * DIM2];   // feat as half2 (u32)
__device__ unsigned g_h16[2][N_NODES * DIM2];   // ping-pong hidden, half2
__device__ unsigned g_agg_pk[N_NODES * DIM];    // agg packed (lo<<16)|hi bf16
__device__ unsigned g_W_pk[LAYERS * DIM * DIM]; // W packed [l][k][n]
__device__ int      g_deg_out[N_NODES];
__device__ int      g_deg_in[N_NODES];
__device__ float    g_norm_src[N_NODES];
__device__ int      g_row_ptr[N_NODES + 1];
__device__ int      g_cursor[N_NODES];
__device__ int2     g_csr[N_EDGES];
__device__ int      g_partial[SCAN_BLOCKS];

// ---------------- bf16 hi/lo packing ----------------
__device__ __forceinline__ unsigned pack_bf16x2(float x) {
    __nv_bfloat16 h = __float2bfloat16(x);
    float r = x - __bfloat162float(h);
    __nv_bfloat16 l = __float2bfloat16(r);
    return ((unsigned)__bfloat16_as_ushort(l) << 16) |
            (unsigned)__bfloat16_as_ushort(h);
}

// bf16 mma: D(16x8,f32) += A(16x16,bf16) * B(16x8,bf16)
__device__ __forceinline__ void mma_bf16(float c[4], const uint32_t a[4],
                                         uint32_t b0, uint32_t b1) {
    asm volatile(
        "mma.sync.aligned.m16n8k16.row.col.f32.bf16.bf16.f32 "
        "{%0,%1,%2,%3}, {%4,%5,%6,%7}, {%8,%9}, {%0,%1,%2,%3};"
        : "+f"(c[0]), "+f"(c[1]), "+f"(c[2]), "+f"(c[3])
        : "r"(a[0]), "r"(a[1]), "r"(a[2]), "r"(a[3]), "r"(b0), "r"(b1));
}

// ---------------- feat -> fp16 (once) ----------------
__global__ void feat_to_h16_kernel(const float* __restrict__ feat) {
    int i = blockIdx.x * blockDim.x + threadIdx.x;
    if (i < N_NODES * DIM2) {
        float2 f = ((const float2*)feat)[i];
        __half2 h = __floats2half2_rn(f.x, f.y);
        g_feat16[i] = *(unsigned*)&h;
    }
}

// ---------------- W -> packed bf16 hi/lo ([l][k][n]) ----------------
__global__ void split_w_kernel(const float* __restrict__ W) {
    int i = blockIdx.x * blockDim.x + threadIdx.x;
    if (i < LAYERS * DIM * DIM)
        g_W_pk[i] = pack_bf16x2(W[i]);
}

// ---------------- degree computation ----------------
__global__ void zero_deg_kernel() {
    int i = blockIdx.x * blockDim.x + threadIdx.x;
    if (i < N_NODES) { g_deg_out[i] = 0; g_deg_in[i] = 0; }
}

__global__ void count_deg_kernel(const int* __restrict__ src,
                                 const int* __restrict__ dst) {
    int e = blockIdx.x * blockDim.x + threadIdx.x;
    if (e < N_EDGES) {
        atomicAdd(&g_deg_out[src[e]], 1);
        atomicAdd(&g_deg_in[dst[e]], 1);
    }
}

// ---------------- decoupled scan ----------------
__global__ __launch_bounds__(SCAN_CHUNK)
void scan_partial_kernel() {
    __shared__ int wsum[SCAN_CHUNK / 32];
    int tid = threadIdx.x, lane = tid & 31, wid = tid >> 5;
    int i = blockIdx.x * SCAN_CHUNK + tid;
    int v = (i < N_NODES) ? g_deg_in[i] : 0;
    #pragma unroll
    for (int o = 16; o > 0; o >>= 1) v += __shfl_down_sync(0xFFFFFFFFu, v, o);
    if (lane == 0) wsum[wid] = v;
    __syncthreads();
    if (tid == 0) {
        int s = 0;
        #pragma unroll
        for (int w = 0; w < SCAN_CHUNK / 32; w++) s += wsum[w];
        g_partial[blockIdx.x] = s;
    }
}

__global__ __launch_bounds__(256)
void scan_offsets_kernel() {
    __shared__ int wsum[8];
    int tid = threadIdx.x, lane = tid & 31, wid = tid >> 5;
    int v = (tid < SCAN_BLOCKS) ? g_partial[tid] : 0;
    int orig = v;
    #pragma unroll
    for (int o = 1; o < 32; o <<= 1) {
        int n = __shfl_up_sync(0xFFFFFFFFu, v, o);
        if (lane >= o) v += n;
    }
    if (lane == 31) wsum[wid] = v;
    __syncthreads();
    if (wid == 0 && lane < 8) {
        int s = wsum[lane];
        #pragma unroll
        for (int o = 1; o < 8; o <<= 1) {
            int n = __shfl_up_sync(0xFFu, s, o);
            if (lane >= o) s += n;
        }
        wsum[lane] = s;
    }
    __syncthreads();
    int excl = v - orig + (wid > 0 ? wsum[wid - 1] : 0);
    if (tid < SCAN_BLOCKS) g_partial[tid] = excl;
}

__global__ __launch_bounds__(SCAN_CHUNK)
void scan_write_kernel() {
    __shared__ int wsum[SCAN_CHUNK / 32];
    int tid = threadIdx.x, lane = tid & 31, wid = tid >> 5;
    int i = blockIdx.x * SCAN_CHUNK + tid;
    int orig = (i < N_NODES) ? g_deg_in[i] : 0;
    int v = orig;
    #pragma unroll
    for (int o = 1; o < 32; o <<= 1) {
        int n = __shfl_up_sync(0xFFFFFFFFu, v, o);
        if (lane >= o) v += n;
    }
    if (lane == 31) wsum[wid] = v;
    __syncthreads();
    if (wid == 0 && lane < SCAN_CHUNK / 32) {
        int s = wsum[lane];
        #pragma unroll
        for (int o = 1; o < SCAN_CHUNK / 32; o <<= 1) {
            int n = __shfl_up_sync(0xFFu, s, o);
            if (lane >= o) s += n;
        }
        wsum[lane] = s;
    }
    __syncthreads();
    int excl = v - orig + (wid > 0 ? wsum[wid - 1] : 0) + g_partial[blockIdx.x];
    if (i < N_NODES) {
        g_row_ptr[i] = excl;
        g_cursor[i]  = excl;
        if (i == N_NODES - 1) g_row_ptr[N_NODES] = excl + orig;
        g_norm_src[i] = rsqrtf(fmaxf((float)g_deg_out[i], 1.0f));
    }
}

__global__ void scatter_edges_kernel(const int* __restrict__ src,
                                     const int* __restrict__ dst) {
    int e = blockIdx.x * blockDim.x + threadIdx.x;
    if (e < N_EDGES) {
        int s = src[e];
        int d = dst[e];
        int pos = atomicAdd(&g_cursor[d], 1);
        float nd = rsqrtf(fmaxf((float)g_deg_in[d], 1.0f));
        g_csr[pos] = make_int2(s, __float_as_int(g_norm_src[s] * nd));
    }
}

// ---------------- SpMM (CSR gather, fp16 rows): one warp per dst node -------
// Gathers half2 rows (256 B/row), fp32 accumulate, emits packed bf16 hi/lo.
__global__ __launch_bounds__(256)
void spmm_csr_kernel(int in_sel) {
    int node = blockIdx.x * (blockDim.x >> 5) + (threadIdx.x >> 5);
    if (node >= N_NODES) return;
    int lane = threadIdx.x & 31;

    const unsigned* __restrict__ h = (in_sel < 0) ? g_feat16 : g_h16[in_sel];
    const int2* __restrict__ csr = g_csr;

    int beg = g_row_ptr[node];
    int end = g_row_ptr[node + 1];

    float4 s0 = make_float4(0.f, 0.f, 0.f, 0.f);
    float4 s1 = make_float4(0.f, 0.f, 0.f, 0.f);
    float4 s2 = make_float4(0.f, 0.f, 0.f, 0.f);
    float4 s3 = make_float4(0.f, 0.f, 0.f, 0.f);

    int i = beg;
    for (; i + 3 < end; i += 4) {
        int2 e0 = csr[i];
        int2 e1 = csr[i + 1];
        int2 e2 = csr[i + 2];
        int2 e3 = csr[i + 3];
        uint2 v0 = ((const uint2*)(h + (size_t)e0.x * DIM2))[lane];
        uint2 v1 = ((const uint2*)(h + (size_t)e1.x * DIM2))[lane];
        uint2 v2 = ((const uint2*)(h + (size_t)e2.x * DIM2))[lane];
        uint2 v3 = ((const uint2*)(h + (size_t)e3.x * DIM2))[lane];
        float w0 = __int_as_float(e0.y);
        float w1 = __int_as_float(e1.y);
        float w2 = __int_as_float(e2.y);
        float w3 = __int_as_float(e3.y);
        float2 a, bq;
        a = __half22float2(*(__half2*)&v0.x); bq = __half22float2(*(__half2*)&v0.y);
        s0.x += a.x * w0; s0.y += a.y * w0; s0.z += bq.x * w0; s0.w += bq.y * w0;
        a = __half22float2(*(__half2*)&v1.x); bq = __half22float2(*(__half2*)&v1.y);
        s1.x += a.x * w1; s1.y += a.y * w1; s1.z += bq.x * w1; s1.w += bq.y * w1;
        a = __half22float2(*(__half2*)&v2.x); bq = __half22float2(*(__half2*)&v2.y);
        s2.x += a.x * w2; s2.y += a.y * w2; s2.z += bq.x * w2; s2.w += bq.y * w2;
        a = __half22float2(*(__half2*)&v3.x); bq = __half22float2(*(__half2*)&v3.y);
        s3.x += a.x * w3; s3.y += a.y * w3; s3.z += bq.x * w3; s3.w += bq.y * w3;
    }
    for (; i < end; i++) {
        int2 e0 = csr[i];
        float w0 = __int_as_float(e0.y);
        uint2 v0 = ((const uint2*)(h + (size_t)e0.x * DIM2))[lane];
        float2 a = __half22float2(*(__half2*)&v0.x);
        float2 bq = __half22float2(*(__half2*)&v0.y);
        s0.x += a.x * w0; s0.y += a.y * w0; s0.z += bq.x * w0; s0.w += bq.y * w0;
    }

    float4 o;
    o.x = (s0.x + s1.x) + (s2.x + s3.x);
    o.y = (s0.y + s1.y) + (s2.y + s3.y);
    o.z = (s0.z + s1.z) + (s2.z + s3.z);
    o.w = (s0.w + s1.w) + (s2.w + s3.w);

    uint4 pk;
    pk.x = pack_bf16x2(o.x);
    pk.y = pack_bf16x2(o.y);
    pk.z = pack_bf16x2(o.z);
    pk.w = pack_bf16x2(o.w);
    ((uint4*)(g_agg_pk + (size_t)node * DIM))[lane] = pk;
}

// ---------------- bf16 tensor GEMM: out = relu(agg @ W + b) ----------------
// 3-pass error-compensated bf16: Ahi*Bhi + Ahi*Blo + Alo*Bhi, fp32 accum.
// Tile: BM=64, BN=128. 128 threads = 4 warps (2M x 2N), warp tile 32x64.
// Output: fp16 half2 to g_h16[out_sel], or fp32 to ext_out for last layer.
__global__ __launch_bounds__(128, 4)
void gemm_bf16_kernel(const float* __restrict__ bias_p,
                      float* __restrict__ ext_out,
                      int layer, int out_sel) {
    __shared__ uint32_t Apk[64 * 36];   // 64 rows x 32 k packed (+4 pad)
    __shared__ uint32_t Wpk[32 * 132];  // 32 k x 128 n packed (+4 pad)

    const unsigned* __restrict__ Wp = g_W_pk + (size_t)layer * DIM * DIM;

    const int tid  = threadIdx.x;
    const int lane = tid & 31;
    const int wrp  = tid >> 5;
    const int wm   = wrp & 1;       // warp's M half (32 rows)
    const int wn   = wrp >> 1;      // warp's N half (64 cols)
    const int gid  = lane >> 2;     // groupID (0..7)
    const int tg   = lane & 3;      // thread-in-group (0..3)
    const int rowBase = blockIdx.x * 64;

    float C[2][8][4];
    #pragma unroll
    for (int mt = 0; mt < 2; mt++)
        #pragma unroll
        for (int nt = 0; nt < 8; nt++)
            #pragma unroll
            for (int q = 0; q < 4; q++) C[mt][nt][q] = 0.0f;

    for (int kc = 0; kc < DIM; kc += 32) {
        if (kc) __syncthreads();   // protect smem reuse

        // stage A chunk: 64 rows x 32 k packed (512 uint4, 4/thread)
        #pragma unroll
        for (int it = 0; it < 4; it++) {
            int f  = tid + it * 128;
            int r  = f >> 3;
            int cc = (f & 7) * 4;
            int grow = rowBase + r;
            uint4 v = make_uint4(0u, 0u, 0u, 0u);
            if (grow < N_NODES)
                v = *(const uint4*)&g_agg_pk[(size_t)grow * DIM + kc + cc];
            *(uint4*)&Apk[r * 36 + cc] = v;
        }
        // stage W chunk: 32 k x 128 n packed (1024 uint4, 8/thread)
        #pragma unroll
        for (int it = 0; it < 8; it++) {
            int f  = tid + it * 128;
            int kk = f >> 5;
            int nn = (f & 31) * 4;
            *(uint4*)&Wpk[kk * 132 + nn] =
                *(const uint4*)&Wp[(size_t)(kc + kk) * DIM + nn];
        }
        __syncthreads();

        #pragma unroll
        for (int k16 = 0; k16 < 32; k16 += 16) {
            uint32_t ah[2][4], al[2][4];
            #pragma unroll
            for (int mt = 0; mt < 2; mt++) {
                int r0 = wm * 32 + mt * 16 + gid;
                int c0 = k16 + tg * 2;
                uint32_t p00 = Apk[r0 * 36 + c0];
                uint32_t p01 = Apk[r0 * 36 + c0 + 1];
                uint32_t p10 = Apk[(r0 + 8) * 36 + c0];
                uint32_t p11 = Apk[(r0 + 8) * 36 + c0 + 1];
                uint32_t p20 = Apk[r0 * 36 + c0 + 8];
                uint32_t p21 = Apk[r0 * 36 + c0 + 9];
                uint32_t p30 = Apk[(r0 + 8) * 36 + c0 + 8];
                uint32_t p31 = Apk[(r0 + 8) * 36 + c0 + 9];
                ah[mt][0] = __byte_perm(p00, p01, 0x5410);
                al[mt][0] = __byte_perm(p00, p01, 0x7632);
                ah[mt][1] = __byte_perm(p10, p11, 0x5410);
                al[mt][1] = __byte_perm(p10, p11, 0x7632);
                ah[mt][2] = __byte_perm(p20, p21, 0x5410);
                al[mt][2] = __byte_perm(p20, p21, 0x7632);
                ah[mt][3] = __byte_perm(p30, p31, 0x5410);
                al[mt][3] = __byte_perm(p30, p31, 0x7632);
            }
            #pragma unroll
            for (int nt = 0; nt < 8; nt++) {
                int n = wn * 64 + nt * 8 + gid;
                int k = k16 + tg * 2;
                uint32_t q00 = Wpk[k * 132 + n];
                uint32_t q01 = Wpk[(k + 1) * 132 + n];
                uint32_t q10 = Wpk[(k + 8) * 132 + n];
                uint32_t q11 = Wpk[(k + 9) * 132 + n];
                uint32_t bh0 = __byte_perm(q00, q01, 0x5410);
                uint32_t bl0 = __byte_perm(q00, q01, 0x7632);
                uint32_t bh1 = __byte_perm(q10, q11, 0x5410);
                uint32_t bl1 = __byte_perm(q10, q11, 0x7632);
                #pragma unroll
                for (int mt = 0; mt < 2; mt++) {
                    mma_bf16(C[mt][nt], ah[mt], bh0, bh1);   // hi*hi
                    mma_bf16(C[mt][nt], ah[mt], bl0, bl1);   // hi*lo
                    mma_bf16(C[mt][nt], al[mt], bh0, bh1);   // lo*hi
                }
            }
        }
    }

    // epilogue: bias + relu; fp16 half2 for hidden layers, fp32 for final.
    unsigned* __restrict__ out16 = (out_sel < 0) ? nullptr : g_h16[out_sel];
    #pragma unroll
    for (int nt = 0; nt < 8; nt++) {
        int col = wn * 64 + nt * 8 + 2 * tg;
        float b0 = bias_p[col];
        float b1 = bias_p[col + 1];
        #pragma unroll
        for (int mt = 0; mt < 2; mt++) {
            int row = rowBase + wm * 32 + mt * 16 + gid;
            float x0 = fmaxf(C[mt][nt][0] + b0, 0.f);
            float y0 = fmaxf(C[mt][nt][1] + b1, 0.f);
            float x1 = fmaxf(C[mt][nt][2] + b0, 0.f);
            float y1 = fmaxf(C[mt][nt][3] + b1, 0.f);
            if (out_sel < 0) {
                if (row < N_NODES)
                    *(float2*)&ext_out[(size_t)row * DIM + col] =
                        make_float2(x0, y0);
                if (row + 8 < N_NODES)
                    *(float2*)&ext_out[(size_t)(row + 8) * DIM + col] =
                        make_float2(x1, y1);
            } else {
                if (row < N_NODES) {
                    __half2 hv = __floats2half2_rn(x0, y0);
                    out16[(size_t)row * DIM2 + (col >> 1)] = *(unsigned*)&hv;
                }
                if (row + 8 < N_NODES) {
                    __half2 hv = __floats2half2_rn(x1, y1);
                    out16[(size_t)(row + 8) * DIM2 + (col >> 1)] = *(unsigned*)&hv;
                }
            }
        }
    }
}

// ---------------- launch ----------------
extern "C" void kernel_launch(void* const* d_in, const int* in_sizes, int n_in,
                              void* d_out, int out_size) {
    const float* feat = (const float*)d_in[0];   // [N, D]
    const int*   src  = (const int*)d_in[1];     // [E]
    const int*   dst  = (const int*)d_in[2];     // [E]
    const float* W    = (const float*)d_in[3];   // [L, D, D]
    const float* b    = (const float*)d_in[4];   // [L, D]
    float* out = (float*)d_out;                  // [N, D]

    (void)in_sizes; (void)n_in; (void)out_size;

    // ---- one-time CSR build + conversions (per launch, graph-capturable) ----
    zero_deg_kernel<<<(N_NODES + 255) / 256, 256>>>();
    count_deg_kernel<<<(N_EDGES + 255) / 256, 256>>>(src, dst);
    scan_partial_kernel<<<SCAN_BLOCKS, SCAN_CHUNK>>>();
    scan_offsets_kernel<<<1, 256>>>();
    scan_write_kernel<<<SCAN_BLOCKS, SCAN_CHUNK>>>();
    scatter_edges_kernel<<<(N_EDGES + 255) / 256, 256>>>(src, dst);
    split_w_kernel<<<(LAYERS * DIM * DIM + 255) / 256, 256>>>(W);
    feat_to_h16_kernel<<<(N_NODES * DIM2 + 255) / 256, 256>>>(feat);

    const int warps_per_block = 256 / 32;
    const int spmm_blocks = (N_NODES + warps_per_block - 1) / warps_per_block;
    const int gemm_blocks = (N_NODES + 63) / 64;   // 782

    for (int l = 0; l < LAYERS; l++) {
        int in_sel  = (l == 0) ? -1 : ((l - 1) & 1);
        int out_sel = (l == LAYERS - 1) ? -1 : (l & 1);

        spmm_csr_kernel<<<spmm_blocks, 256>>>(in_sel);
        gemm_bf16_kernel<<<gemm_blocks, 128>>>(
            b + (size_t)l * DIM, out, l, out_sel);
    }
}

// round 11
// speedup vs baseline: 1.4397x; 1.1221x over previous
#include <cuda_runtime.h>
#include <cuda_fp16.h>
#include <cstdint>

#define N_NODES 50000
#define N_EDGES 800000
#define DIM     128
#define DIM2    64                    // DIM/2 (u32 units per row)
#define LAYERS  5

#define SCAN_BLOCKS 196               // ceil(50000/256)
#define FEAT_BLOCKS 12500             // 50000*64/256
#define WSPL_BLOCKS 160               // 5*64*128/256
#define ZERO_BLOCKS 196

#define FLAG_AGG    (1u << 30)
#define FLAG_PRE    (2u << 30)
#define VAL_MASK    0x3FFFFFFFu

// ---------------- scratch (no allocation allowed) ----------------
__device__ unsigned g_feat16[N_NODES * DIM2];    // feat as half2
__device__ unsigned g_h16[2][N_NODES * DIM2];    // ping-pong hidden, half2
__device__ unsigned g_agg16[N_NODES * DIM2];     // aggregation, half2
__device__ unsigned g_Whl[2][LAYERS * DIM2 * DIM]; // W hi/lo, [l][k2][n] half2(k,k+1)
__device__ int      g_deg_out[N_NODES];
__device__ int      g_deg_in[N_NODES];
__device__ float    g_norm_src[N_NODES];
__device__ int      g_row_ptr[N_NODES + 1];
__device__ int      g_cursor[N_NODES];
__device__ int2     g_csr[N_EDGES];
__device__ unsigned g_scan_state[SCAN_BLOCKS];

// fp16 mma: D(16x8,f32) += A(16x16,f16) * B(16x8,f16)
__device__ __forceinline__ void mma_f16(float c[4], const uint32_t a[4],
                                        uint32_t b0, uint32_t b1) {
    asm volatile(
        "mma.sync.aligned.m16n8k16.row.col.f32.f16.f16.f32 "
        "{%0,%1,%2,%3}, {%4,%5,%6,%7}, {%8,%9}, {%0,%1,%2,%3};"
        : "+f"(c[0]), "+f"(c[1]), "+f"(c[2]), "+f"(c[3])
        : "r"(a[0]), "r"(a[1]), "r"(a[2]), "r"(a[3]), "r"(b0), "r"(b1));
}

// ---------------- fused init: feat->fp16, W split, zero deg/state ----------
__global__ __launch_bounds__(256)
void init_kernel(const float* __restrict__ feat, const float* __restrict__ W) {
    int bid = blockIdx.x;
    if (bid < FEAT_BLOCKS) {
        int i = bid * 256 + threadIdx.x;             // < 3.2M
        float2 f = ((const float2*)feat)[i];
        __half2 h = __floats2half2_rn(f.x, f.y);
        g_feat16[i] = *(unsigned*)&h;
    } else if (bid < FEAT_BLOCKS + WSPL_BLOCKS) {
        int i = (bid - FEAT_BLOCKS) * 256 + threadIdx.x;   // < 40960
        int n  = i & 127;
        int k2 = (i >> 7) & 63;
        int l  = i >> 13;
        float w0 = W[l * DIM * DIM + (2 * k2)     * DIM + n];
        float w1 = W[l * DIM * DIM + (2 * k2 + 1) * DIM + n];
        __half h0 = __float2half_rn(w0);
        __half h1 = __float2half_rn(w1);
        float r0 = w0 - __half2float(h0);
        float r1 = w1 - __half2float(h1);
        __half2 hi = __halves2half2(h0, h1);
        __half2 lo = __floats2half2_rn(r0, r1);
        g_Whl[0][i] = *(unsigned*)&hi;
        g_Whl[1][i] = *(unsigned*)&lo;
    } else {
        int i = (bid - FEAT_BLOCKS - WSPL_BLOCKS) * 256 + threadIdx.x;
        if (i < N_NODES) { g_deg_out[i] = 0; g_deg_in[i] = 0; }
        if (i < SCAN_BLOCKS) g_scan_state[i] = 0u;
    }
}

// ---------------- degree count ----------------
__global__ void count_deg_kernel(const int* __restrict__ src,
                                 const int* __restrict__ dst) {
    int e = blockIdx.x * blockDim.x + threadIdx.x;
    if (e < N_EDGES) {
        atomicAdd(&g_deg_out[src[e]], 1);
        atomicAdd(&g_deg_in[dst[e]], 1);
    }
}

// ---------------- single-kernel decoupled-lookback scan ----------------
// Writes row_ptr, cursor, norm_src in one pass.
__global__ __launch_bounds__(256)
void scan_fused_kernel() {
    __shared__ int wsum[8];
    __shared__ int s_excl;
    int tid  = threadIdx.x;
    int lane = tid & 31;
    int wid  = tid >> 5;
    int bid  = blockIdx.x;
    int i    = bid * 256 + tid;

    int deg = (i < N_NODES) ? g_deg_in[i] : 0;

    // block inclusive scan
    int v = deg;
    #pragma unroll
    for (int o = 1; o < 32; o <<= 1) {
        int n = __shfl_up_sync(0xFFFFFFFFu, v, o);
        if (lane >= o) v += n;
    }
    if (lane == 31) wsum[wid] = v;
    __syncthreads();
    if (wid == 0) {
        int s = (lane < 8) ? wsum[lane] : 0;
        #pragma unroll
        for (int o = 1; o < 8; o <<= 1) {
            int n = __shfl_up_sync(0xFFFFFFFFu, s, o);
            if (lane >= o) s += n;
        }
        if (lane < 8) wsum[lane] = s;
    }
    __syncthreads();
    int incl = v + (wid > 0 ? wsum[wid - 1] : 0);
    int btot = wsum[7];

    // publish aggregate (block 0 publishes prefix directly)
    if (tid == 0) {
        unsigned pub = (bid == 0) ? (FLAG_PRE | (unsigned)btot)
                                  : (FLAG_AGG | (unsigned)btot);
        atomicExch(&g_scan_state[bid], pub);
        if (bid == 0) s_excl = 0;
    }

    // lookback (warp 0)
    if (bid > 0 && wid == 0) {
        int excl = 0;
        int look = bid - 1;
        while (true) {
            int idx = look - lane;
            unsigned s;
            do {
                s = (idx >= 0) ? atomicAdd(&g_scan_state[idx], 0u)
                               : FLAG_PRE;       // idx<0 => prefix of 0
            } while (s == 0u);
            unsigned pmask = __ballot_sync(0xFFFFFFFFu, (s >> 30) == 2u);
            int val;
            if (pmask) {
                int plane = __ffs(pmask) - 1;    // closest predecessor w/ prefix
                val = (lane <= plane) ? (int)(s & VAL_MASK) : 0;
            } else {
                val = (int)(s & VAL_MASK);
            }
            #pragma unroll
            for (int o = 16; o > 0; o >>= 1)
                val += __shfl_down_sync(0xFFFFFFFFu, val, o);
            excl += __shfl_sync(0xFFFFFFFFu, val, 0);
            if (pmask) break;
            look -= 32;
        }
        if (lane == 0) {
            s_excl = excl;
            atomicExch(&g_scan_state[bid], FLAG_PRE | (unsigned)(excl + btot));
        }
    }
    __syncthreads();

    int excl_t = s_excl + incl - deg;
    if (i < N_NODES) {
        g_row_ptr[i] = excl_t;
        g_cursor[i]  = excl_t;
        if (i == N_NODES - 1) g_row_ptr[N_NODES] = excl_t + deg;
        g_norm_src[i] = rsqrtf(fmaxf((float)g_deg_out[i], 1.0f));
    }
}

// ---------------- scatter edges into packed CSR --------------------------
__global__ void scatter_edges_kernel(const int* __restrict__ src,
                                     const int* __restrict__ dst) {
    int e = blockIdx.x * blockDim.x + threadIdx.x;
    if (e < N_EDGES) {
        int s = src[e];
        int d = dst[e];
        int pos = atomicAdd(&g_cursor[d], 1);
        float nd = rsqrtf(fmaxf((float)g_deg_in[d], 1.0f));
        g_csr[pos] = make_int2(s, __float_as_int(g_norm_src[s] * nd));
    }
}

// ---------------- SpMM (CSR gather, fp16 rows): one warp per dst node ----
// fp32 accumulate; emits fp16 agg.
__global__ __launch_bounds__(256)
void spmm_csr_kernel(int in_sel) {
    int node = blockIdx.x * (blockDim.x >> 5) + (threadIdx.x >> 5);
    if (node >= N_NODES) return;
    int lane = threadIdx.x & 31;

    const unsigned* __restrict__ h = (in_sel < 0) ? g_feat16 : g_h16[in_sel];
    const int2* __restrict__ csr = g_csr;

    int beg = g_row_ptr[node];
    int end = g_row_ptr[node + 1];

    float4 s0 = make_float4(0.f, 0.f, 0.f, 0.f);
    float4 s1 = make_float4(0.f, 0.f, 0.f, 0.f);
    float4 s2 = make_float4(0.f, 0.f, 0.f, 0.f);
    float4 s3 = make_float4(0.f, 0.f, 0.f, 0.f);

    int i = beg;
    for (; i + 3 < end; i += 4) {
        int2 e0 = csr[i];
        int2 e1 = csr[i + 1];
        int2 e2 = csr[i + 2];
        int2 e3 = csr[i + 3];
        uint2 v0 = ((const uint2*)(h + (size_t)e0.x * DIM2))[lane];
        uint2 v1 = ((const uint2*)(h + (size_t)e1.x * DIM2))[lane];
        uint2 v2 = ((const uint2*)(h + (size_t)e2.x * DIM2))[lane];
        uint2 v3 = ((const uint2*)(h + (size_t)e3.x * DIM2))[lane];
        float w0 = __int_as_float(e0.y);
        float w1 = __int_as_float(e1.y);
        float w2 = __int_as_float(e2.y);
        float w3 = __int_as_float(e3.y);
        float2 a, bq;
        a = __half22float2(*(__half2*)&v0.x); bq = __half22float2(*(__half2*)&v0.y);
        s0.x += a.x * w0; s0.y += a.y * w0; s0.z += bq.x * w0; s0.w += bq.y * w0;
        a = __half22float2(*(__half2*)&v1.x); bq = __half22float2(*(__half2*)&v1.y);
        s1.x += a.x * w1; s1.y += a.y * w1; s1.z += bq.x * w1; s1.w += bq.y * w1;
        a = __half22float2(*(__half2*)&v2.x); bq = __half22float2(*(__half2*)&v2.y);
        s2.x += a.x * w2; s2.y += a.y * w2; s2.z += bq.x * w2; s2.w += bq.y * w2;
        a = __half22float2(*(__half2*)&v3.x); bq = __half22float2(*(__half2*)&v3.y);
        s3.x += a.x * w3; s3.y += a.y * w3; s3.z += bq.x * w3; s3.w += bq.y * w3;
    }
    for (; i < end; i++) {
        int2 e0 = csr[i];
        float w0 = __int_as_float(e0.y);
        uint2 v0 = ((const uint2*)(h + (size_t)e0.x * DIM2))[lane];
        float2 a = __half22float2(*(__half2*)&v0.x);
        float2 bq = __half22float2(*(__half2*)&v0.y);
        s0.x += a.x * w0; s0.y += a.y * w0; s0.z += bq.x * w0; s0.w += bq.y * w0;
    }

    float4 o;
    o.x = (s0.x + s1.x) + (s2.x + s3.x);
    o.y = (s0.y + s1.y) + (s2.y + s3.y);
    o.z = (s0.z + s1.z) + (s2.z + s3.z);
    o.w = (s0.w + s1.w) + (s2.w + s3.w);

    __half2 h01 = __floats2half2_rn(o.x, o.y);
    __half2 h23 = __floats2half2_rn(o.z, o.w);
    uint2 pk;
    pk.x = *(unsigned*)&h01;
    pk.y = *(unsigned*)&h23;
    ((uint2*)(g_agg16 + (size_t)node * DIM2))[lane] = pk;
}

// ---------------- fp16 tensor GEMM: out = relu(agg @ W + b) --------------
// 2-pass W-compensated fp16: A_f16 * (Whi + Wlo), fp32 accum.
// Tile: BM=64, BN=128. 128 threads = 4 warps (2M x 2N), warp tile 32x64.
__global__ __launch_bounds__(128, 4)
void gemm_fp16_kernel(const float* __restrict__ bias_p,
                      float* __restrict__ ext_out,
                      int layer, int out_sel) {
    __shared__ uint32_t Apk[64 * 20];    // 64 rows x 16 u32 (32 k) + pad
    __shared__ uint32_t Whi[16 * 136];   // 16 k2 x 128 n + pad
    __shared__ uint32_t Wlo[16 * 136];

    const unsigned* __restrict__ Wh = g_Whl[0] + (size_t)layer * DIM2 * DIM;
    const unsigned* __restrict__ Wl = g_Whl[1] + (size_t)layer * DIM2 * DIM;

    const int tid  = threadIdx.x;
    const int lane = tid & 31;
    const int wrp  = tid >> 5;
    const int wm   = wrp & 1;
    const int wn   = wrp >> 1;
    const int gid  = lane >> 2;
    const int tg   = lane & 3;
    const int rowBase = blockIdx.x * 64;

    float C[2][8][4];
    #pragma unroll
    for (int mt = 0; mt < 2; mt++)
        #pragma unroll
        for (int nt = 0; nt < 8; nt++)
            #pragma unroll
            for (int q = 0; q < 4; q++) C[mt][nt][q] = 0.0f;

    for (int kc2 = 0; kc2 < DIM2; kc2 += 16) {   // 4 chunks of 32 k
        if (kc2) __syncthreads();

        // stage A chunk: 64 rows x 16 u32 (256 uint4, 2/thread)
        #pragma unroll
        for (int it = 0; it < 2; it++) {
            int f  = tid + it * 128;
            int r  = f >> 2;
            int cc = (f & 3) * 4;
            int grow = rowBase + r;
            uint4 v = make_uint4(0u, 0u, 0u, 0u);
            if (grow < N_NODES)
                v = *(const uint4*)&g_agg16[(size_t)grow * DIM2 + kc2 + cc];
            *(uint4*)&Apk[r * 20 + cc] = v;
        }
        // stage W hi/lo chunks: 16 k2 x 128 n each (512 uint4 each, 4/thread)
        #pragma unroll
        for (int it = 0; it < 4; it++) {
            int f  = tid + it * 128;
            int kk = f >> 5;
            int nn = (f & 31) * 4;
            *(uint4*)&Whi[kk * 136 + nn] =
                *(const uint4*)&Wh[(size_t)(kc2 + kk) * DIM + nn];
            *(uint4*)&Wlo[kk * 136 + nn] =
                *(const uint4*)&Wl[(size_t)(kc2 + kk) * DIM + nn];
        }
        __syncthreads();

        #pragma unroll
        for (int k8 = 0; k8 < 2; k8++) {         // two m16n8k16 k-groups
            uint32_t a[2][4];
            #pragma unroll
            for (int mt = 0; mt < 2; mt++) {
                int r0 = wm * 32 + mt * 16 + gid;
                int c0 = k8 * 8 + tg;
                a[mt][0] = Apk[r0 * 20 + c0];
                a[mt][1] = Apk[(r0 + 8) * 20 + c0];
                a[mt][2] = Apk[r0 * 20 + c0 + 4];
                a[mt][3] = Apk[(r0 + 8) * 20 + c0 + 4];
            }
            #pragma unroll
            for (int nt = 0; nt < 8; nt++) {
                int n = wn * 64 + nt * 8 + gid;
                int k = k8 * 8 + tg;
                uint32_t bh0 = Whi[k * 136 + n];
                uint32_t bh1 = Whi[(k + 4) * 136 + n];
                uint32_t bl0 = Wlo[k * 136 + n];
                uint32_t bl1 = Wlo[(k + 4) * 136 + n];
                #pragma unroll
                for (int mt = 0; mt < 2; mt++) {
                    mma_f16(C[mt][nt], a[mt], bh0, bh1);   // A * Whi
                    mma_f16(C[mt][nt], a[mt], bl0, bl1);   // A * Wlo
                }
            }
        }
    }

    // epilogue: bias + relu; fp16 half2 for hidden layers, fp32 for final.
    unsigned* __restrict__ out16 = (out_sel < 0) ? nullptr : g_h16[out_sel];
    #pragma unroll
    for (int nt = 0; nt < 8; nt++) {
        int col = wn * 64 + nt * 8 + 2 * tg;
        float b0 = bias_p[col];
        float b1 = bias_p[col + 1];
        #pragma unroll
        for (int mt = 0; mt < 2; mt++) {
            int row = rowBase + wm * 32 + mt * 16 + gid;
            float x0 = fmaxf(C[mt][nt][0] + b0, 0.f);
            float y0 = fmaxf(C[mt][nt][1] + b1, 0.f);
            float x1 = fmaxf(C[mt][nt][2] + b0, 0.f);
            float y1 = fmaxf(C[mt][nt][3] + b1, 0.f);
            if (out_sel < 0) {
                if (row < N_NODES)
                    *(float2*)&ext_out[(size_t)row * DIM + col] =
                        make_float2(x0, y0);
                if (row + 8 < N_NODES)
                    *(float2*)&ext_out[(size_t)(row + 8) * DIM + col] =
                        make_float2(x1, y1);
            } else {
                if (row < N_NODES) {
                    __half2 hv = __floats2half2_rn(x0, y0);
                    out16[(size_t)row * DIM2 + (col >> 1)] = *(unsigned*)&hv;
                }
                if (row + 8 < N_NODES) {
                    __half2 hv = __floats2half2_rn(x1, y1);
                    out16[(size_t)(row + 8) * DIM2 + (col >> 1)] = *(unsigned*)&hv;
                }
            }
        }
    }
}

// ---------------- launch ----------------
extern "C" void kernel_launch(void* const* d_in, const int* in_sizes, int n_in,
                              void* d_out, int out_size) {
    const float* feat = (const float*)d_in[0];   // [N, D]
    const int*   src  = (const int*)d_in[1];     // [E]
    const int*   dst  = (const int*)d_in[2];     // [E]
    const float* W    = (const float*)d_in[3];   // [L, D, D]
    const float* b    = (const float*)d_in[4];   // [L, D]
    float* out = (float*)d_out;                  // [N, D]

    (void)in_sizes; (void)n_in; (void)out_size;

    // ---- prologue: 4 kernels ----
    init_kernel<<<FEAT_BLOCKS + WSPL_BLOCKS + ZERO_BLOCKS, 256>>>(feat, W);
    count_deg_kernel<<<(N_EDGES + 255) / 256, 256>>>(src, dst);
    scan_fused_kernel<<<SCAN_BLOCKS, 256>>>();
    scatter_edges_kernel<<<(N_EDGES + 255) / 256, 256>>>(src, dst);

    const int warps_per_block = 256 / 32;
    const int spmm_blocks = (N_NODES + warps_per_block - 1) / warps_per_block;
    const int gemm_blocks = (N_NODES + 63) / 64;   // 782

    for (int l = 0; l < LAYERS; l++) {
        int in_sel  = (l == 0) ? -1 : ((l - 1) & 1);
        int out_sel = (l == LAYERS - 1) ? -1 : (l & 1);

        spmm_csr_kernel<<<spmm_blocks, 256>>>(in_sel);
        gemm_fp16_kernel<<<gemm_blocks, 128>>>(
            b + (size_t)l * DIM, out, l, out_sel);
    }
}

// round 12
// speedup vs baseline: 1.5535x; 1.0790x over previous
#include <cuda_runtime.h>
#include <cuda_fp16.h>
#include <cstdint>

#define N_NODES 50000
#define N_EDGES 800000
#define DIM     128
#define DIM2    64                    // DIM/2 (u32 units per row)
#define LAYERS  5

#define SCAN_BLOCKS 196               // ceil(50000/256)
#define FEAT_BLOCKS 12500             // 50000*64/256
#define WSPL_BLOCKS 160               // 5*64*128/256
#define ZERO_BLOCKS 196

#define FLAG_AGG    (1u << 30)
#define FLAG_PRE    (2u << 30)
#define VAL_MASK    0x3FFFFFFFu

// ---------------- scratch (no allocation allowed) ----------------
__device__ unsigned g_feat16[N_NODES * DIM2];    // feat as half2
__device__ unsigned g_h16[2][N_NODES * DIM2];    // ping-pong hidden, half2
__device__ unsigned g_agg16[N_NODES * DIM2];     // aggregation, half2
__device__ unsigned g_Whl[2][LAYERS * DIM2 * DIM]; // W hi/lo, [l][k2][n]
__device__ int      g_deg_out[N_NODES];
__device__ int      g_deg_in[N_NODES];
__device__ float    g_norm_src[N_NODES];
__device__ int      g_row_ptr[N_NODES + 1];
__device__ int      g_cursor[N_NODES];
__device__ int2     g_csr[N_EDGES];
__device__ unsigned g_scan_state[SCAN_BLOCKS];

// fp16 mma: D(16x8,f32) += A(16x16,f16) * B(16x8,f16)
__device__ __forceinline__ void mma_f16(float c[4], const uint32_t a[4],
                                        uint32_t b0, uint32_t b1) {
    asm volatile(
        "mma.sync.aligned.m16n8k16.row.col.f32.f16.f16.f32 "
        "{%0,%1,%2,%3}, {%4,%5,%6,%7}, {%8,%9}, {%0,%1,%2,%3};"
        : "+f"(c[0]), "+f"(c[1]), "+f"(c[2]), "+f"(c[3])
        : "r"(a[0]), "r"(a[1]), "r"(a[2]), "r"(a[3]), "r"(b0), "r"(b1));
}

// ---------------- fused init: feat->fp16, W split, zero deg/state ----------
__global__ __launch_bounds__(256)
void init_kernel(const float* __restrict__ feat, const float* __restrict__ W) {
    int bid = blockIdx.x;
    if (bid < FEAT_BLOCKS) {
        int i = bid * 256 + threadIdx.x;             // < 3.2M
        float2 f = ((const float2*)feat)[i];
        __half2 h = __floats2half2_rn(f.x, f.y);
        g_feat16[i] = *(unsigned*)&h;
    } else if (bid < FEAT_BLOCKS + WSPL_BLOCKS) {
        int i = (bid - FEAT_BLOCKS) * 256 + threadIdx.x;   // < 40960
        int n  = i & 127;
        int k2 = (i >> 7) & 63;
        int l  = i >> 13;
        float w0 = W[l * DIM * DIM + (2 * k2)     * DIM + n];
        float w1 = W[l * DIM * DIM + (2 * k2 + 1) * DIM + n];
        __half h0 = __float2half_rn(w0);
        __half h1 = __float2half_rn(w1);
        float r0 = w0 - __half2float(h0);
        float r1 = w1 - __half2float(h1);
        __half2 hi = __halves2half2(h0, h1);
        __half2 lo = __floats2half2_rn(r0, r1);
        g_Whl[0][i] = *(unsigned*)&hi;
        g_Whl[1][i] = *(unsigned*)&lo;
    } else {
        int i = (bid - FEAT_BLOCKS - WSPL_BLOCKS) * 256 + threadIdx.x;
        if (i < N_NODES) { g_deg_out[i] = 0; g_deg_in[i] = 0; }
        if (i < SCAN_BLOCKS) g_scan_state[i] = 0u;
    }
}

// ---------------- degree count ----------------
__global__ void count_deg_kernel(const int* __restrict__ src,
                                 const int* __restrict__ dst) {
    int e = blockIdx.x * blockDim.x + threadIdx.x;
    if (e < N_EDGES) {
        atomicAdd(&g_deg_out[src[e]], 1);
        atomicAdd(&g_deg_in[dst[e]], 1);
    }
}

// ---------------- single-kernel decoupled-lookback scan ----------------
__global__ __launch_bounds__(256)
void scan_fused_kernel() {
    __shared__ int wsum[8];
    __shared__ int s_excl;
    int tid  = threadIdx.x;
    int lane = tid & 31;
    int wid  = tid >> 5;
    int bid  = blockIdx.x;
    int i    = bid * 256 + tid;

    int deg = (i < N_NODES) ? g_deg_in[i] : 0;

    // block inclusive scan
    int v = deg;
    #pragma unroll
    for (int o = 1; o < 32; o <<= 1) {
        int n = __shfl_up_sync(0xFFFFFFFFu, v, o);
        if (lane >= o) v += n;
    }
    if (lane == 31) wsum[wid] = v;
    __syncthreads();
    if (wid == 0) {
        int s = (lane < 8) ? wsum[lane] : 0;
        #pragma unroll
        for (int o = 1; o < 8; o <<= 1) {
            int n = __shfl_up_sync(0xFFFFFFFFu, s, o);
            if (lane >= o) s += n;
        }
        if (lane < 8) wsum[lane] = s;
    }
    __syncthreads();
    int incl = v + (wid > 0 ? wsum[wid - 1] : 0);
    int btot = wsum[7];

    if (tid == 0) {
        unsigned pub = (bid == 0) ? (FLAG_PRE | (unsigned)btot)
                                  : (FLAG_AGG | (unsigned)btot);
        atomicExch(&g_scan_state[bid], pub);
        if (bid == 0) s_excl = 0;
    }

    if (bid > 0 && wid == 0) {
        int excl = 0;
        int look = bid - 1;
        while (true) {
            int idx = look - lane;
            unsigned s;
            do {
                s = (idx >= 0) ? atomicAdd(&g_scan_state[idx], 0u)
                               : FLAG_PRE;
            } while (s == 0u);
            unsigned pmask = __ballot_sync(0xFFFFFFFFu, (s >> 30) == 2u);
            int val;
            if (pmask) {
                int plane = __ffs(pmask) - 1;
                val = (lane <= plane) ? (int)(s & VAL_MASK) : 0;
            } else {
                val = (int)(s & VAL_MASK);
            }
            #pragma unroll
            for (int o = 16; o > 0; o >>= 1)
                val += __shfl_down_sync(0xFFFFFFFFu, val, o);
            excl += __shfl_sync(0xFFFFFFFFu, val, 0);
            if (pmask) break;
            look -= 32;
        }
        if (lane == 0) {
            s_excl = excl;
            atomicExch(&g_scan_state[bid], FLAG_PRE | (unsigned)(excl + btot));
        }
    }
    __syncthreads();

    int excl_t = s_excl + incl - deg;
    if (i < N_NODES) {
        g_row_ptr[i] = excl_t;
        g_cursor[i]  = excl_t;
        if (i == N_NODES - 1) g_row_ptr[N_NODES] = excl_t + deg;
        g_norm_src[i] = rsqrtf(fmaxf((float)g_deg_out[i], 1.0f));
    }
}

// ---------------- scatter edges into packed CSR --------------------------
__global__ void scatter_edges_kernel(const int* __restrict__ src,
                                     const int* __restrict__ dst) {
    int e = blockIdx.x * blockDim.x + threadIdx.x;
    if (e < N_EDGES) {
        int s = src[e];
        int d = dst[e];
        int pos = atomicAdd(&g_cursor[d], 1);
        float nd = rsqrtf(fmaxf((float)g_deg_in[d], 1.0f));
        g_csr[pos] = make_int2(s, __float_as_int(g_norm_src[s] * nd));
    }
}

// ---------------- SpMM (CSR gather, fp16 rows): one warp per dst node ----
// HFMA2 products + 4-edge half2 partial sums, promoted to fp32 per group.
__global__ __launch_bounds__(256)
void spmm_csr_kernel(int in_sel) {
    int node = blockIdx.x * (blockDim.x >> 5) + (threadIdx.x >> 5);
    if (node >= N_NODES) return;
    int lane = threadIdx.x & 31;

    const unsigned* __restrict__ h = (in_sel < 0) ? g_feat16 : g_h16[in_sel];
    const int2* __restrict__ csr = g_csr;

    int beg = g_row_ptr[node];
    int end = g_row_ptr[node + 1];

    float4 acc = make_float4(0.f, 0.f, 0.f, 0.f);

    int i = beg;
    for (; i + 3 < end; i += 4) {
        int2 e0 = csr[i];
        int2 e1 = csr[i + 1];
        int2 e2 = csr[i + 2];
        int2 e3 = csr[i + 3];
        uint2 v0 = ((const uint2*)(h + (size_t)e0.x * DIM2))[lane];
        uint2 v1 = ((const uint2*)(h + (size_t)e1.x * DIM2))[lane];
        uint2 v2 = ((const uint2*)(h + (size_t)e2.x * DIM2))[lane];
        uint2 v3 = ((const uint2*)(h + (size_t)e3.x * DIM2))[lane];
        __half2 w0 = __float2half2_rn(__int_as_float(e0.y));
        __half2 w1 = __float2half2_rn(__int_as_float(e1.y));
        __half2 w2 = __float2half2_rn(__int_as_float(e2.y));
        __half2 w3 = __float2half2_rn(__int_as_float(e3.y));

        __half2 p0 = __hmul2(*(__half2*)&v0.x, w0);
        __half2 p1 = __hmul2(*(__half2*)&v0.y, w0);
        p0 = __hfma2(*(__half2*)&v1.x, w1, p0);
        p1 = __hfma2(*(__half2*)&v1.y, w1, p1);
        p0 = __hfma2(*(__half2*)&v2.x, w2, p0);
        p1 = __hfma2(*(__half2*)&v2.y, w2, p1);
        p0 = __hfma2(*(__half2*)&v3.x, w3, p0);
        p1 = __hfma2(*(__half2*)&v3.y, w3, p1);

        float2 f0 = __half22float2(p0);
        float2 f1 = __half22float2(p1);
        acc.x += f0.x; acc.y += f0.y; acc.z += f1.x; acc.w += f1.y;
    }
    // remainder in fp32 (cheap, <=3 edges)
    for (; i < end; i++) {
        int2 e0 = csr[i];
        float w = __int_as_float(e0.y);
        uint2 v0 = ((const uint2*)(h + (size_t)e0.x * DIM2))[lane];
        float2 a = __half22float2(*(__half2*)&v0.x);
        float2 b = __half22float2(*(__half2*)&v0.y);
        acc.x += a.x * w; acc.y += a.y * w; acc.z += b.x * w; acc.w += b.y * w;
    }

    __half2 h01 = __floats2half2_rn(acc.x, acc.y);
    __half2 h23 = __floats2half2_rn(acc.z, acc.w);
    uint2 pk;
    pk.x = *(unsigned*)&h01;
    pk.y = *(unsigned*)&h23;
    ((uint2*)(g_agg16 + (size_t)node * DIM2))[lane] = pk;
}

// ---------------- fp16 tensor GEMM: out = relu(agg @ W + b) --------------
// 2-pass W-compensated fp16: A_f16 * (Whi + Wlo), fp32 accum.
__global__ __launch_bounds__(128, 4)
void gemm_fp16_kernel(const float* __restrict__ bias_p,
                      float* __restrict__ ext_out,
                      int layer, int out_sel) {
    __shared__ uint32_t Apk[64 * 20];    // 64 rows x 16 u32 (32 k) + pad
    __shared__ uint32_t Whi[16 * 136];   // 16 k2 x 128 n + pad
    __shared__ uint32_t Wlo[16 * 136];

    const unsigned* __restrict__ Wh = g_Whl[0] + (size_t)layer * DIM2 * DIM;
    const unsigned* __restrict__ Wl = g_Whl[1] + (size_t)layer * DIM2 * DIM;

    const int tid  = threadIdx.x;
    const int lane = tid & 31;
    const int wrp  = tid >> 5;
    const int wm   = wrp & 1;
    const int wn   = wrp >> 1;
    const int gid  = lane >> 2;
    const int tg   = lane & 3;
    const int rowBase = blockIdx.x * 64;

    float C[2][8][4];
    #pragma unroll
    for (int mt = 0; mt < 2; mt++)
        #pragma unroll
        for (int nt = 0; nt < 8; nt++)
            #pragma unroll
            for (int q = 0; q < 4; q++) C[mt][nt][q] = 0.0f;

    for (int kc2 = 0; kc2 < DIM2; kc2 += 16) {   // 4 chunks of 32 k
        if (kc2) __syncthreads();

        #pragma unroll
        for (int it = 0; it < 2; it++) {
            int f  = tid + it * 128;
            int r  = f >> 2;
            int cc = (f & 3) * 4;
            int grow = rowBase + r;
            uint4 v = make_uint4(0u, 0u, 0u, 0u);
            if (grow < N_NODES)
                v = *(const uint4*)&g_agg16[(size_t)grow * DIM2 + kc2 + cc];
            *(uint4*)&Apk[r * 20 + cc] = v;
        }
        #pragma unroll
        for (int it = 0; it < 4; it++) {
            int f  = tid + it * 128;
            int kk = f >> 5;
            int nn = (f & 31) * 4;
            *(uint4*)&Whi[kk * 136 + nn] =
                *(const uint4*)&Wh[(size_t)(kc2 + kk) * DIM + nn];
            *(uint4*)&Wlo[kk * 136 + nn] =
                *(const uint4*)&Wl[(size_t)(kc2 + kk) * DIM + nn];
        }
        __syncthreads();

        #pragma unroll
        for (int k8 = 0; k8 < 2; k8++) {
            uint32_t a[2][4];
            #pragma unroll
            for (int mt = 0; mt < 2; mt++) {
                int r0 = wm * 32 + mt * 16 + gid;
                int c0 = k8 * 8 + tg;
                a[mt][0] = Apk[r0 * 20 + c0];
                a[mt][1] = Apk[(r0 + 8) * 20 + c0];
                a[mt][2] = Apk[r0 * 20 + c0 + 4];
                a[mt][3] = Apk[(r0 + 8) * 20 + c0 + 4];
            }
            #pragma unroll
            for (int nt = 0; nt < 8; nt++) {
                int n = wn * 64 + nt * 8 + gid;
                int k = k8 * 8 + tg;
                uint32_t bh0 = Whi[k * 136 + n];
                uint32_t bh1 = Whi[(k + 4) * 136 + n];
                uint32_t bl0 = Wlo[k * 136 + n];
                uint32_t bl1 = Wlo[(k + 4) * 136 + n];
                #pragma unroll
                for (int mt = 0; mt < 2; mt++) {
                    mma_f16(C[mt][nt], a[mt], bh0, bh1);   // A * Whi
                    mma_f16(C[mt][nt], a[mt], bl0, bl1);   // A * Wlo
                }
            }
        }
    }

    unsigned* __restrict__ out16 = (out_sel < 0) ? nullptr : g_h16[out_sel];
    #pragma unroll
    for (int nt = 0; nt < 8; nt++) {
        int col = wn * 64 + nt * 8 + 2 * tg;
        float b0 = bias_p[col];
        float b1 = bias_p[col + 1];
        #pragma unroll
        for (int mt = 0; mt < 2; mt++) {
            int row = rowBase + wm * 32 + mt * 16 + gid;
            float x0 = fmaxf(C[mt][nt][0] + b0, 0.f);
            float y0 = fmaxf(C[mt][nt][1] + b1, 0.f);
            float x1 = fmaxf(C[mt][nt][2] + b0, 0.f);
            float y1 = fmaxf(C[mt][nt][3] + b1, 0.f);
            if (out_sel < 0) {
                if (row < N_NODES)
                    *(float2*)&ext_out[(size_t)row * DIM + col] =
                        make_float2(x0, y0);
                if (row + 8 < N_NODES)
                    *(float2*)&ext_out[(size_t)(row + 8) * DIM + col] =
                        make_float2(x1, y1);
            } else {
                if (row < N_NODES) {
                    __half2 hv = __floats2half2_rn(x0, y0);
                    out16[(size_t)row * DIM2 + (col >> 1)] = *(unsigned*)&hv;
                }
                if (row + 8 < N_NODES) {
                    __half2 hv = __floats2half2_rn(x1, y1);
                    out16[(size_t)(row + 8) * DIM2 + (col >> 1)] = *(unsigned*)&hv;
                }
            }
        }
    }
}

// ---------------- launch ----------------
extern "C" void kernel_launch(void* const* d_in, const int* in_sizes, int n_in,
                              void* d_out, int out_size) {
    const float* feat = (const float*)d_in[0];   // [N, D]
    const int*   src  = (const int*)d_in[1];     // [E]
    const int*   dst  = (const int*)d_in[2];     // [E]
    const float* W    = (const float*)d_in[3];   // [L, D, D]
    const float* b    = (const float*)d_in[4];   // [L, D]
    float* out = (float*)d_out;                  // [N, D]

    (void)in_sizes; (void)n_in; (void)out_size;

    init_kernel<<<FEAT_BLOCKS + WSPL_BLOCKS + ZERO_BLOCKS, 256>>>(feat, W);
    count_deg_kernel<<<(N_EDGES + 255) / 256, 256>>>(src, dst);
    scan_fused_kernel<<<SCAN_BLOCKS, 256>>>();
    scatter_edges_kernel<<<(N_EDGES + 255) / 256, 256>>>(src, dst);

    const int warps_per_block = 256 / 32;
    const int spmm_blocks = (N_NODES + warps_per_block - 1) / warps_per_block;
    const int gemm_blocks = (N_NODES + 63) / 64;   // 782

    for (int l = 0; l < LAYERS; l++) {
        int in_sel  = (l == 0) ? -1 : ((l - 1) & 1);
        int out_sel = (l == LAYERS - 1) ? -1 : (l & 1);

        spmm_csr_kernel<<<spmm_blocks, 256>>>(in_sel);
        gemm_fp16_kernel<<<gemm_blocks, 128>>>(
            b + (size_t)l * DIM, out, l, out_sel);
    }
}

// round 13
// speedup vs baseline: 1.5876x; 1.0220x over previous
#include <cuda_runtime.h>
#include <cuda_fp16.h>
#include <cstdint>

#define N_NODES 50000
#define N_EDGES 800000
#define DIM     128
#define DIM2    64                    // DIM/2 (u32 units per row)
#define LAYERS  5

#define SCAN_BLOCKS 196               // ceil(50000/256)
#define FEAT_BLOCKS 12500             // 50000*64/256
#define WSPL_BLOCKS 160               // 5*64*128/256
#define ZERO_BLOCKS 196

#define FLAG_AGG    (1u << 30)
#define FLAG_PRE    (2u << 30)
#define VAL_MASK    0x3FFFFFFFu

// ---------------- scratch (no allocation allowed) ----------------
__device__ unsigned g_feat16[N_NODES * DIM2];    // feat as half2
__device__ unsigned g_h16[2][N_NODES * DIM2];    // ping-pong hidden, half2
__device__ unsigned g_agg16[N_NODES * DIM2];     // aggregation, half2
__device__ unsigned g_Whl[2][LAYERS * DIM2 * DIM]; // W hi/lo, [l][k2][n]
__device__ int      g_deg_out[N_NODES];
__device__ int      g_deg_in[N_NODES];
__device__ float    g_norm_src[N_NODES];
__device__ int      g_row_ptr[N_NODES + 1];
__device__ int      g_cursor[N_NODES];
__device__ int2     g_csr[N_EDGES];
__device__ unsigned g_scan_state[SCAN_BLOCKS];

// fp16 mma: D(16x8,f32) += A(16x16,f16) * B(16x8,f16)
__device__ __forceinline__ void mma_f16(float c[4], const uint32_t a[4],
                                        uint32_t b0, uint32_t b1) {
    asm volatile(
        "mma.sync.aligned.m16n8k16.row.col.f32.f16.f16.f32 "
        "{%0,%1,%2,%3}, {%4,%5,%6,%7}, {%8,%9}, {%0,%1,%2,%3};"
        : "+f"(c[0]), "+f"(c[1]), "+f"(c[2]), "+f"(c[3])
        : "r"(a[0]), "r"(a[1]), "r"(a[2]), "r"(a[3]), "r"(b0), "r"(b1));
}

// ---------------- fused init: feat->fp16, W split, zero deg/state ----------
__global__ __launch_bounds__(256)
void init_kernel(const float* __restrict__ feat, const float* __restrict__ W) {
    int bid = blockIdx.x;
    if (bid < FEAT_BLOCKS) {
        int i = bid * 256 + threadIdx.x;             // < 3.2M
        float2 f = ((const float2*)feat)[i];
        __half2 h = __floats2half2_rn(f.x, f.y);
        g_feat16[i] = *(unsigned*)&h;
    } else if (bid < FEAT_BLOCKS + WSPL_BLOCKS) {
        int i = (bid - FEAT_BLOCKS) * 256 + threadIdx.x;   // < 40960
        int n  = i & 127;
        int k2 = (i >> 7) & 63;
        int l  = i >> 13;
        float w0 = W[l * DIM * DIM + (2 * k2)     * DIM + n];
        float w1 = W[l * DIM * DIM + (2 * k2 + 1) * DIM + n];
        __half h0 = __float2half_rn(w0);
        __half h1 = __float2half_rn(w1);
        float r0 = w0 - __half2float(h0);
        float r1 = w1 - __half2float(h1);
        __half2 hi = __halves2half2(h0, h1);
        __half2 lo = __floats2half2_rn(r0, r1);
        g_Whl[0][i] = *(unsigned*)&hi;
        g_Whl[1][i] = *(unsigned*)&lo;
    } else {
        int i = (bid - FEAT_BLOCKS - WSPL_BLOCKS) * 256 + threadIdx.x;
        if (i < N_NODES) { g_deg_out[i] = 0; g_deg_in[i] = 0; }
        if (i < SCAN_BLOCKS) g_scan_state[i] = 0u;
    }
}

// ---------------- degree count ----------------
__global__ void count_deg_kernel(const int* __restrict__ src,
                                 const int* __restrict__ dst) {
    int e = blockIdx.x * blockDim.x + threadIdx.x;
    if (e < N_EDGES) {
        atomicAdd(&g_deg_out[src[e]], 1);
        atomicAdd(&g_deg_in[dst[e]], 1);
    }
}

// ---------------- single-kernel decoupled-lookback scan ----------------
__global__ __launch_bounds__(256)
void scan_fused_kernel() {
    __shared__ int wsum[8];
    __shared__ int s_excl;
    int tid  = threadIdx.x;
    int lane = tid & 31;
    int wid  = tid >> 5;
    int bid  = blockIdx.x;
    int i    = bid * 256 + tid;

    int deg = (i < N_NODES) ? g_deg_in[i] : 0;

    int v = deg;
    #pragma unroll
    for (int o = 1; o < 32; o <<= 1) {
        int n = __shfl_up_sync(0xFFFFFFFFu, v, o);
        if (lane >= o) v += n;
    }
    if (lane == 31) wsum[wid] = v;
    __syncthreads();
    if (wid == 0) {
        int s = (lane < 8) ? wsum[lane] : 0;
        #pragma unroll
        for (int o = 1; o < 8; o <<= 1) {
            int n = __shfl_up_sync(0xFFFFFFFFu, s, o);
            if (lane >= o) s += n;
        }
        if (lane < 8) wsum[lane] = s;
    }
    __syncthreads();
    int incl = v + (wid > 0 ? wsum[wid - 1] : 0);
    int btot = wsum[7];

    if (tid == 0) {
        unsigned pub = (bid == 0) ? (FLAG_PRE | (unsigned)btot)
                                  : (FLAG_AGG | (unsigned)btot);
        atomicExch(&g_scan_state[bid], pub);
        if (bid == 0) s_excl = 0;
    }

    if (bid > 0 && wid == 0) {
        int excl = 0;
        int look = bid - 1;
        while (true) {
            int idx = look - lane;
            unsigned s;
            do {
                s = (idx >= 0) ? atomicAdd(&g_scan_state[idx], 0u)
                               : FLAG_PRE;
            } while (s == 0u);
            unsigned pmask = __ballot_sync(0xFFFFFFFFu, (s >> 30) == 2u);
            int val;
            if (pmask) {
                int plane = __ffs(pmask) - 1;
                val = (lane <= plane) ? (int)(s & VAL_MASK) : 0;
            } else {
                val = (int)(s & VAL_MASK);
            }
            #pragma unroll
            for (int o = 16; o > 0; o >>= 1)
                val += __shfl_down_sync(0xFFFFFFFFu, val, o);
            excl += __shfl_sync(0xFFFFFFFFu, val, 0);
            if (pmask) break;
            look -= 32;
        }
        if (lane == 0) {
            s_excl = excl;
            atomicExch(&g_scan_state[bid], FLAG_PRE | (unsigned)(excl + btot));
        }
    }
    __syncthreads();

    int excl_t = s_excl + incl - deg;
    if (i < N_NODES) {
        g_row_ptr[i] = excl_t;
        g_cursor[i]  = excl_t;
        if (i == N_NODES - 1) g_row_ptr[N_NODES] = excl_t + deg;
        g_norm_src[i] = rsqrtf(fmaxf((float)g_deg_out[i], 1.0f));
    }
}

// ---------------- scatter edges into packed CSR --------------------------
__global__ void scatter_edges_kernel(const int* __restrict__ src,
                                     const int* __restrict__ dst) {
    int e = blockIdx.x * blockDim.x + threadIdx.x;
    if (e < N_EDGES) {
        int s = src[e];
        int d = dst[e];
        int pos = atomicAdd(&g_cursor[d], 1);
        float nd = rsqrtf(fmaxf((float)g_deg_in[d], 1.0f));
        g_csr[pos] = make_int2(s, __float_as_int(g_norm_src[s] * nd));
    }
}

// ---------------- SpMM (CSR gather, fp16 rows): one warp per dst node ----
// 8-edge groups: two independent 4-term HFMA2 chains -> more loads in flight.
__global__ __launch_bounds__(256)
void spmm_csr_kernel(int in_sel) {
    int node = blockIdx.x * (blockDim.x >> 5) + (threadIdx.x >> 5);
    if (node >= N_NODES) return;
    int lane = threadIdx.x & 31;

    const unsigned* __restrict__ h = (in_sel < 0) ? g_feat16 : g_h16[in_sel];
    const int2* __restrict__ csr = g_csr;

    int beg = g_row_ptr[node];
    int end = g_row_ptr[node + 1];

    float4 acc = make_float4(0.f, 0.f, 0.f, 0.f);

    int i = beg;
    for (; i + 7 < end; i += 8) {
        int2 e0 = csr[i];
        int2 e1 = csr[i + 1];
        int2 e2 = csr[i + 2];
        int2 e3 = csr[i + 3];
        int2 e4 = csr[i + 4];
        int2 e5 = csr[i + 5];
        int2 e6 = csr[i + 6];
        int2 e7 = csr[i + 7];
        uint2 v0 = ((const uint2*)(h + (size_t)e0.x * DIM2))[lane];
        uint2 v1 = ((const uint2*)(h + (size_t)e1.x * DIM2))[lane];
        uint2 v2 = ((const uint2*)(h + (size_t)e2.x * DIM2))[lane];
        uint2 v3 = ((const uint2*)(h + (size_t)e3.x * DIM2))[lane];
        uint2 v4 = ((const uint2*)(h + (size_t)e4.x * DIM2))[lane];
        uint2 v5 = ((const uint2*)(h + (size_t)e5.x * DIM2))[lane];
        uint2 v6 = ((const uint2*)(h + (size_t)e6.x * DIM2))[lane];
        uint2 v7 = ((const uint2*)(h + (size_t)e7.x * DIM2))[lane];

        __half2 w0 = __float2half2_rn(__int_as_float(e0.y));
        __half2 w1 = __float2half2_rn(__int_as_float(e1.y));
        __half2 w2 = __float2half2_rn(__int_as_float(e2.y));
        __half2 w3 = __float2half2_rn(__int_as_float(e3.y));
        __half2 w4 = __float2half2_rn(__int_as_float(e4.y));
        __half2 w5 = __float2half2_rn(__int_as_float(e5.y));
        __half2 w6 = __float2half2_rn(__int_as_float(e6.y));
        __half2 w7 = __float2half2_rn(__int_as_float(e7.y));

        // chain A: edges 0-3
        __half2 p0 = __hmul2(*(__half2*)&v0.x, w0);
        __half2 p1 = __hmul2(*(__half2*)&v0.y, w0);
        p0 = __hfma2(*(__half2*)&v1.x, w1, p0);
        p1 = __hfma2(*(__half2*)&v1.y, w1, p1);
        p0 = __hfma2(*(__half2*)&v2.x, w2, p0);
        p1 = __hfma2(*(__half2*)&v2.y, w2, p1);
        p0 = __hfma2(*(__half2*)&v3.x, w3, p0);
        p1 = __hfma2(*(__half2*)&v3.y, w3, p1);
        // chain B: edges 4-7
        __half2 q0 = __hmul2(*(__half2*)&v4.x, w4);
        __half2 q1 = __hmul2(*(__half2*)&v4.y, w4);
        q0 = __hfma2(*(__half2*)&v5.x, w5, q0);
        q1 = __hfma2(*(__half2*)&v5.y, w5, q1);
        q0 = __hfma2(*(__half2*)&v6.x, w6, q0);
        q1 = __hfma2(*(__half2*)&v6.y, w6, q1);
        q0 = __hfma2(*(__half2*)&v7.x, w7, q0);
        q1 = __hfma2(*(__half2*)&v7.y, w7, q1);

        float2 f0 = __half22float2(p0);
        float2 f1 = __half22float2(p1);
        float2 g0 = __half22float2(q0);
        float2 g1 = __half22float2(q1);
        acc.x += f0.x + g0.x; acc.y += f0.y + g0.y;
        acc.z += f1.x + g1.x; acc.w += f1.y + g1.y;
    }
    for (; i + 3 < end; i += 4) {
        int2 e0 = csr[i];
        int2 e1 = csr[i + 1];
        int2 e2 = csr[i + 2];
        int2 e3 = csr[i + 3];
        uint2 v0 = ((const uint2*)(h + (size_t)e0.x * DIM2))[lane];
        uint2 v1 = ((const uint2*)(h + (size_t)e1.x * DIM2))[lane];
        uint2 v2 = ((const uint2*)(h + (size_t)e2.x * DIM2))[lane];
        uint2 v3 = ((const uint2*)(h + (size_t)e3.x * DIM2))[lane];
        __half2 w0 = __float2half2_rn(__int_as_float(e0.y));
        __half2 w1 = __float2half2_rn(__int_as_float(e1.y));
        __half2 w2 = __float2half2_rn(__int_as_float(e2.y));
        __half2 w3 = __float2half2_rn(__int_as_float(e3.y));
        __half2 p0 = __hmul2(*(__half2*)&v0.x, w0);
        __half2 p1 = __hmul2(*(__half2*)&v0.y, w0);
        p0 = __hfma2(*(__half2*)&v1.x, w1, p0);
        p1 = __hfma2(*(__half2*)&v1.y, w1, p1);
        p0 = __hfma2(*(__half2*)&v2.x, w2, p0);
        p1 = __hfma2(*(__half2*)&v2.y, w2, p1);
        p0 = __hfma2(*(__half2*)&v3.x, w3, p0);
        p1 = __hfma2(*(__half2*)&v3.y, w3, p1);
        float2 f0 = __half22float2(p0);
        float2 f1 = __half22float2(p1);
        acc.x += f0.x; acc.y += f0.y; acc.z += f1.x; acc.w += f1.y;
    }
    for (; i < end; i++) {
        int2 e0 = csr[i];
        float w = __int_as_float(e0.y);
        uint2 v0 = ((const uint2*)(h + (size_t)e0.x * DIM2))[lane];
        float2 a = __half22float2(*(__half2*)&v0.x);
        float2 b = __half22float2(*(__half2*)&v0.y);
        acc.x += a.x * w; acc.y += a.y * w; acc.z += b.x * w; acc.w += b.y * w;
    }

    __half2 h01 = __floats2half2_rn(acc.x, acc.y);
    __half2 h23 = __floats2half2_rn(acc.z, acc.w);
    uint2 pk;
    pk.x = *(unsigned*)&h01;
    pk.y = *(unsigned*)&h23;
    ((uint2*)(g_agg16 + (size_t)node * DIM2))[lane] = pk;
}

// ---------------- fp16 tensor GEMM: out = relu(agg @ W + b) --------------
// 2-pass W-compensated fp16. Tile: BM=128, BN=128. 256 threads = 8 warps
// (4M x 2N), warp tile 32x64. Halves W L2 traffic vs BM=64.
__global__ __launch_bounds__(256, 2)
void gemm_fp16_kernel(const float* __restrict__ bias_p,
                      float* __restrict__ ext_out,
                      int layer, int out_sel) {
    __shared__ uint32_t Apk[128 * 20];   // 128 rows x 16 u32 (32 k) + pad
    __shared__ uint32_t Whi[16 * 136];   // 16 k2 x 128 n + pad
    __shared__ uint32_t Wlo[16 * 136];

    const unsigned* __restrict__ Wh = g_Whl[0] + (size_t)layer * DIM2 * DIM;
    const unsigned* __restrict__ Wl = g_Whl[1] + (size_t)layer * DIM2 * DIM;

    const int tid  = threadIdx.x;
    const int lane = tid & 31;
    const int wrp  = tid >> 5;
    const int wm   = wrp & 3;       // 4 M quarters (32 rows each)
    const int wn   = wrp >> 2;      // 2 N halves (64 cols each)
    const int gid  = lane >> 2;
    const int tg   = lane & 3;
    const int rowBase = blockIdx.x * 128;

    float C[2][8][4];
    #pragma unroll
    for (int mt = 0; mt < 2; mt++)
        #pragma unroll
        for (int nt = 0; nt < 8; nt++)
            #pragma unroll
            for (int q = 0; q < 4; q++) C[mt][nt][q] = 0.0f;

    for (int kc2 = 0; kc2 < DIM2; kc2 += 16) {   // 4 chunks of 32 k
        if (kc2) __syncthreads();

        // stage A chunk: 128 rows x 16 u32 (512 uint4, 2/thread)
        #pragma unroll
        for (int it = 0; it < 2; it++) {
            int f  = tid + it * 256;
            int r  = f >> 2;
            int cc = (f & 3) * 4;
            int grow = rowBase + r;
            uint4 v = make_uint4(0u, 0u, 0u, 0u);
            if (grow < N_NODES)
                v = *(const uint4*)&g_agg16[(size_t)grow * DIM2 + kc2 + cc];
            *(uint4*)&Apk[r * 20 + cc] = v;
        }
        // stage W hi/lo chunks: 512 uint4 each (2/thread each)
        #pragma unroll
        for (int it = 0; it < 2; it++) {
            int f  = tid + it * 256;
            int kk = f >> 5;
            int nn = (f & 31) * 4;
            *(uint4*)&Whi[kk * 136 + nn] =
                *(const uint4*)&Wh[(size_t)(kc2 + kk) * DIM + nn];
            *(uint4*)&Wlo[kk * 136 + nn] =
                *(const uint4*)&Wl[(size_t)(kc2 + kk) * DIM + nn];
        }
        __syncthreads();

        #pragma unroll
        for (int k8 = 0; k8 < 2; k8++) {
            uint32_t a[2][4];
            #pragma unroll
            for (int mt = 0; mt < 2; mt++) {
                int r0 = wm * 32 + mt * 16 + gid;
                int c0 = k8 * 8 + tg;
                a[mt][0] = Apk[r0 * 20 + c0];
                a[mt][1] = Apk[(r0 + 8) * 20 + c0];
                a[mt][2] = Apk[r0 * 20 + c0 + 4];
                a[mt][3] = Apk[(r0 + 8) * 20 + c0 + 4];
            }
            #pragma unroll
            for (int nt = 0; nt < 8; nt++) {
                int n = wn * 64 + nt * 8 + gid;
                int k = k8 * 8 + tg;
                uint32_t bh0 = Whi[k * 136 + n];
                uint32_t bh1 = Whi[(k + 4) * 136 + n];
                uint32_t bl0 = Wlo[k * 136 + n];
                uint32_t bl1 = Wlo[(k + 4) * 136 + n];
                #pragma unroll
                for (int mt = 0; mt < 2; mt++) {
                    mma_f16(C[mt][nt], a[mt], bh0, bh1);   // A * Whi
                    mma_f16(C[mt][nt], a[mt], bl0, bl1);   // A * Wlo
                }
            }
        }
    }

    unsigned* __restrict__ out16 = (out_sel < 0) ? nullptr : g_h16[out_sel];
    #pragma unroll
    for (int nt = 0; nt < 8; nt++) {
        int col = wn * 64 + nt * 8 + 2 * tg;
        float b0 = bias_p[col];
        float b1 = bias_p[col + 1];
        #pragma unroll
        for (int mt = 0; mt < 2; mt++) {
            int row = rowBase + wm * 32 + mt * 16 + gid;
            float x0 = fmaxf(C[mt][nt][0] + b0, 0.f);
            float y0 = fmaxf(C[mt][nt][1] + b1, 0.f);
            float x1 = fmaxf(C[mt][nt][2] + b0, 0.f);
            float y1 = fmaxf(C[mt][nt][3] + b1, 0.f);
            if (out_sel < 0) {
                if (row < N_NODES)
                    *(float2*)&ext_out[(size_t)row * DIM + col] =
                        make_float2(x0, y0);
                if (row + 8 < N_NODES)
                    *(float2*)&ext_out[(size_t)(row + 8) * DIM + col] =
                        make_float2(x1, y1);
            } else {
                if (row < N_NODES) {
                    __half2 hv = __floats2half2_rn(x0, y0);
                    out16[(size_t)row * DIM2 + (col >> 1)] = *(unsigned*)&hv;
                }
                if (row + 8 < N_NODES) {
                    __half2 hv = __floats2half2_rn(x1, y1);
                    out16[(size_t)(row + 8) * DIM2 + (col >> 1)] = *(unsigned*)&hv;
                }
            }
        }
    }
}

// ---------------- launch ----------------
extern "C" void kernel_launch(void* const* d_in, const int* in_sizes, int n_in,
                              void* d_out, int out_size) {
    const float* feat = (const float*)d_in[0];   // [N, D]
    const int*   src  = (const int*)d_in[1];     // [E]
    const int*   dst  = (const int*)d_in[2];     // [E]
    const float* W    = (const float*)d_in[3];   // [L, D, D]
    const float* b    = (const float*)d_in[4];   // [L, D]
    float* out = (float*)d_out;                  // [N, D]

    (void)in_sizes; (void)n_in; (void)out_size;

    init_kernel<<<FEAT_BLOCKS + WSPL_BLOCKS + ZERO_BLOCKS, 256>>>(feat, W);
    count_deg_kernel<<<(N_EDGES + 255) / 256, 256>>>(src, dst);
    scan_fused_kernel<<<SCAN_BLOCKS, 256>>>();
    scatter_edges_kernel<<<(N_EDGES + 255) / 256, 256>>>(src, dst);

    const int warps_per_block = 256 / 32;
    const int spmm_blocks = (N_NODES + warps_per_block - 1) / warps_per_block;
    const int gemm_blocks = (N_NODES + 127) / 128;   // 391

    for (int l = 0; l < LAYERS; l++) {
        int in_sel  = (l == 0) ? -1 : ((l - 1) & 1);
        int out_sel = (l == LAYERS - 1) ? -1 : (l & 1);

        spmm_csr_kernel<<<spmm_blocks, 256>>>(in_sel);
        gemm_fp16_kernel<<<gemm_blocks, 256>>>(
            b + (size_t)l * DIM, out, l, out_sel);
    }
}